// round 6
// baseline (speedup 1.0000x reference)
#include <cuda_runtime.h>
#include <cuda_bf16.h>
#include <stdint.h>

#define B_    8
#define L_    4096
#define D_    1024
#define A_    256
#define LC_   4352      // A_ + L_
#define KEEP_ 256
#define NSLICE 17       // salience partial slices (17 * 256 rows = 4352)
#define GSLICE 8        // gather partial slices   (8 * 32 rows = 256)

// -------- scratch (device globals; no allocation allowed) --------
__device__ float g_sal[B_ * LC_];
__device__ float g_part[B_ * NSLICE * D_];   // salience per-block column sums
__device__ float g_kpart[B_ * GSLICE * D_];  // gather per-block kept column sums
__device__ int   g_topidx[B_ * KEEP_];
__device__ float g_ctx[B_ * D_];
__device__ float g_proj[B_ * D_];

// ---------------- K1: salience + per-block partial column sums ----------------
// grid: (NSLICE, B_), block 512 (16 warps). 256 rows/block, 16 rows/warp. ONE wave.
__global__ void k_salience(const float* __restrict__ x,
                           const float* __restrict__ active,
                           const float* __restrict__ wsal) {
    __shared__ float s_col[D_];
    const int b    = blockIdx.y;
    const int tid  = threadIdx.x;
    const int warp = tid >> 5;
    const int lane = tid & 31;

    for (int i = tid; i < D_; i += blockDim.x) s_col[i] = 0.f;

    float4 ws[8];
#pragma unroll
    for (int k = 0; k < 8; k++)
        ws[k] = *(const float4*)(wsal + k * 128 + lane * 4);
    float4 cs[8];
#pragma unroll
    for (int k = 0; k < 8; k++) cs[k] = make_float4(0.f, 0.f, 0.f, 0.f);

    __syncthreads();

    const int row0 = blockIdx.x * 256 + warp * 16;
#pragma unroll
    for (int r = 0; r < 16; r++) {
        const int t = row0 + r;
        const float* src = (t < A_)
            ? active + ((size_t)b * A_ + t) * D_
            : x      + ((size_t)b * L_ + (t - A_)) * D_;
        float dot = 0.f;
#pragma unroll
        for (int k = 0; k < 8; k++) {
            float4 v = *(const float4*)(src + k * 128 + lane * 4);
            dot += v.x * ws[k].x + v.y * ws[k].y + v.z * ws[k].z + v.w * ws[k].w;
            cs[k].x += v.x; cs[k].y += v.y; cs[k].z += v.z; cs[k].w += v.w;
        }
#pragma unroll
        for (int o = 16; o > 0; o >>= 1)
            dot += __shfl_down_sync(0xffffffffu, dot, o);
        if (lane == 0) g_sal[b * LC_ + t] = dot;
    }

#pragma unroll
    for (int k = 0; k < 8; k++) {
        int d0 = k * 128 + lane * 4;
        atomicAdd(&s_col[d0 + 0], cs[k].x);
        atomicAdd(&s_col[d0 + 1], cs[k].y);
        atomicAdd(&s_col[d0 + 2], cs[k].z);
        atomicAdd(&s_col[d0 + 3], cs[k].w);
    }
    __syncthreads();
    float* dst = g_part + ((size_t)b * NSLICE + blockIdx.x) * D_;
    for (int i = tid; i < D_ / 4; i += blockDim.x)
        *(float4*)(dst + i * 4) = *(const float4*)(&s_col[i * 4]);
}

// ---------------- K2: exact top-256 (radix select), sorted ascending ----------------
__device__ __forceinline__ unsigned int order_key(float f) {
    unsigned int u = __float_as_uint(f);
    return u ^ ((u >> 31) ? 0xFFFFFFFFu : 0x80000000u);
}

__global__ void k_topk() {
    const int b    = blockIdx.x;
    const int tid  = threadIdx.x;           // 1024 threads
    const int lane = tid & 31;
    const int warp = tid >> 5;

    __shared__ unsigned int skeys[LC_];
    __shared__ unsigned int hist[256];
    __shared__ int          out_idx[KEEP_];
    __shared__ unsigned int wsum[32];
    __shared__ unsigned int s_prefix;
    __shared__ int          s_krem;

    for (int i = tid; i < LC_; i += 1024)
        skeys[i] = order_key(g_sal[b * LC_ + i]);
    if (tid == 0) { s_prefix = 0u; s_krem = KEEP_; }
    __syncthreads();

    // 4-pass radix select, bucket scan by warp 0 (shuffle suffix-scan)
    for (int pass = 0; pass < 4; pass++) {
        const int shift = 24 - 8 * pass;
        if (tid < 256) hist[tid] = 0u;
        __syncthreads();
        const unsigned int pfx = s_prefix;
        const int krem = s_krem;
        for (int i = tid; i < LC_; i += 1024) {
            unsigned int k = skeys[i];
            if (pass == 0 || (k >> (shift + 8)) == pfx)
                atomicAdd(&hist[(k >> shift) & 255u], 1u);
        }
        __syncthreads();
        if (warp == 0) {
            unsigned int h[8], suf[8];
            unsigned int acc = 0u;
#pragma unroll
            for (int j = 7; j >= 0; j--) { h[j] = hist[lane * 8 + j]; acc += h[j]; suf[j] = acc; }
            const unsigned int tot = acc;
            unsigned int inc = tot;
#pragma unroll
            for (int off = 1; off < 32; off <<= 1) {
                unsigned int v = __shfl_down_sync(0xffffffffu, inc, off);
                if (lane + off < 32) inc += v;
            }
            const unsigned int after = inc - tot;  // sum over lanes > lane
#pragma unroll
            for (int j = 0; j < 8; j++) {
                unsigned int S  = after + suf[j];
                unsigned int Sn = after + (j < 7 ? suf[j + 1] : 0u);
                if (S >= (unsigned int)krem && Sn < (unsigned int)krem) {
                    s_prefix = (pfx << 8) | (unsigned int)(lane * 8 + j);
                    s_krem   = krem - (int)Sn;
                }
            }
        }
        __syncthreads();
    }

    const unsigned int thr = s_prefix;
    const unsigned int rem = (unsigned int)s_krem;

    // blocked (gt,eq) pair prefix scan; writes kept indices in ascending order
    const int base = tid * 5;                 // 1024*5 = 5120 >= LC_
    unsigned int keys_l[5];
    unsigned int gt = 0u, eq = 0u;
#pragma unroll
    for (int j = 0; j < 5; j++) {
        const int i = base + j;
        unsigned int k = (i < LC_) ? skeys[i] : 0u;
        keys_l[j] = k;
        if (i < LC_) { gt += (k > thr); eq += (k == thr); }
    }
    const unsigned int pair = (gt << 16) | eq;
    unsigned int inc = pair;
#pragma unroll
    for (int off = 1; off < 32; off <<= 1) {
        unsigned int v = __shfl_up_sync(0xffffffffu, inc, off);
        if (lane >= off) inc += v;
    }
    const unsigned int excl = inc - pair;
    if (lane == 31) wsum[warp] = inc;
    __syncthreads();
    if (warp == 0) {
        unsigned int v = wsum[lane];
        unsigned int winc = v;
#pragma unroll
        for (int off = 1; off < 32; off <<= 1) {
            unsigned int t = __shfl_up_sync(0xffffffffu, winc, off);
            if (lane >= off) winc += t;
        }
        wsum[lane] = winc - v;   // exclusive
    }
    __syncthreads();
    const unsigned int basepair = excl + wsum[warp];
    unsigned int gpref = basepair >> 16;
    unsigned int epref = basepair & 0xFFFFu;
#pragma unroll
    for (int j = 0; j < 5; j++) {
        const int i = base + j;
        if (i < LC_) {
            const unsigned int k = keys_l[j];
            if (k > thr) {
                out_idx[gpref + (epref < rem ? epref : rem)] = i;
                gpref++;
            } else if (k == thr) {
                if (epref < rem) out_idx[gpref + epref] = i;
                epref++;
            }
        }
    }
    __syncthreads();
    if (tid < KEEP_) g_topidx[b * KEEP_ + tid] = out_idx[tid];
}

// ---------------- K3: gather kept rows + per-block kept column sums ----------------
// grid: (GSLICE, B_) = (8, B_), block 1024 (32 warps); warp w copies row blk*32+w
__global__ void k_gather(const float* __restrict__ x,
                         const float* __restrict__ active,
                         float* __restrict__ new_active_out) {
    __shared__ float s_col[D_];
    const int b    = blockIdx.y;
    const int tid  = threadIdx.x;
    const int warp = tid >> 5;
    const int lane = tid & 31;
    const int row  = blockIdx.x * 32 + warp;

    for (int i = tid; i < D_; i += blockDim.x) s_col[i] = 0.f;

    const int idx = g_topidx[b * KEEP_ + row];
    const float* src = (idx < A_)
        ? active + ((size_t)b * A_ + idx) * D_
        : x      + ((size_t)b * L_ + (idx - A_)) * D_;
    float* dst = new_active_out + ((size_t)b * KEEP_ + row) * D_;

    float4 v[8];
#pragma unroll
    for (int k = 0; k < 8; k++)
        v[k] = *(const float4*)(src + k * 128 + lane * 4);
    __syncthreads();
#pragma unroll
    for (int k = 0; k < 8; k++) {
        *(float4*)(dst + k * 128 + lane * 4) = v[k];
        int d0 = k * 128 + lane * 4;
        atomicAdd(&s_col[d0 + 0], v[k].x);
        atomicAdd(&s_col[d0 + 1], v[k].y);
        atomicAdd(&s_col[d0 + 2], v[k].z);
        atomicAdd(&s_col[d0 + 3], v[k].w);
    }
    __syncthreads();
    float* kp = g_kpart + ((size_t)b * GSLICE + blockIdx.x) * D_;
    for (int i = tid; i < D_ / 4; i += blockDim.x)
        *(float4*)(kp + i * 4) = *(const float4*)(&s_col[i * 4]);
}

// ---------------- K4: reduce partials -> cold_new + ctx ----------------
// grid (D_/64, B_) = (16, B_), block 512: 8 threads cooperate per d (64 d per block)
__global__ void k_ctx(const float* __restrict__ cold,
                      float* __restrict__ cold_out) {
    __shared__ float st[8][64];
    __shared__ float sk[8][64];
    const int b  = blockIdx.y;
    const int d0 = blockIdx.x * 64;
    const int dx = threadIdx.x & 63;
    const int sy = threadIdx.x >> 6;

    float tot = 0.f;
    const float* p = g_part + (size_t)b * NSLICE * D_ + d0 + dx;
#pragma unroll
    for (int s = sy; s < NSLICE; s += 8) tot += p[(size_t)s * D_];

    float ks = 0.f;
    const float* kp = g_kpart + (size_t)b * GSLICE * D_ + d0 + dx;
    if (sy < GSLICE) ks = kp[(size_t)sy * D_];

    st[sy][dx] = tot;
    sk[sy][dx] = ks;
    __syncthreads();
    if (sy == 0) {
        float t = 0.f, k = 0.f;
#pragma unroll
        for (int s = 0; s < 8; s++) { t += st[s][dx]; k += sk[s][dx]; }
        const int i = b * D_ + d0 + dx;
        const float dropped_mean = (t - k) * (1.0f / (float)(LC_ - KEEP_));
        const float cn = 0.9f * cold[i] + 0.1f * dropped_mean;
        cold_out[i] = cn;
        g_ctx[i] = k * (1.0f / (float)KEEP_) + cn;
    }
}

// ---------------- K5: proj[b,e] = sum_d ctx[b,d] * w_read[e,d] ----------------
// grid 128, block 256 (8 warps, 1 row each)
__global__ void k_gemv(const float* __restrict__ wread) {
    __shared__ float4 sctx[B_ * 256];
    const int tid = threadIdx.x;
    for (int i = tid; i < B_ * 256; i += blockDim.x)
        sctx[i] = *(const float4*)(g_ctx + i * 4);
    __syncthreads();

    const int warp = tid >> 5, lane = tid & 31;
    const int e = blockIdx.x * 8 + warp;
    const float* wr = wread + (size_t)e * D_;
    float acc[B_];
#pragma unroll
    for (int bb = 0; bb < B_; bb++) acc[bb] = 0.f;
#pragma unroll
    for (int k = 0; k < 8; k++) {
        float4 w = *(const float4*)(wr + k * 128 + lane * 4);
#pragma unroll
        for (int bb = 0; bb < B_; bb++) {
            float4 c = sctx[bb * 256 + k * 32 + lane];
            acc[bb] += w.x * c.x + w.y * c.y + w.z * c.z + w.w * c.w;
        }
    }
#pragma unroll
    for (int bb = 0; bb < B_; bb++) {
#pragma unroll
        for (int o = 16; o > 0; o >>= 1)
            acc[bb] += __shfl_down_sync(0xffffffffu, acc[bb], o);
        if (lane == 0) g_proj[bb * D_ + e] = acc[bb];
    }
}

// ---------------- K6: x_out = x + proj (broadcast over l) ----------------
// grid: (L_/32, B_) = (128, B_), block 256; 32 rows per block; MLP-8 prefetch
__global__ void k_addproj(const float* __restrict__ x,
                          float* __restrict__ xout) {
    const int b   = blockIdx.y;
    const int l0  = blockIdx.x * 32;
    const int tid = threadIdx.x;
    const float4 p = *(const float4*)(g_proj + b * D_ + tid * 4);
    const float* xs = x    + ((size_t)b * L_ + l0) * D_ + tid * 4;
    float*       os = xout + ((size_t)b * L_ + l0) * D_ + tid * 4;
#pragma unroll
    for (int rr = 0; rr < 32; rr += 8) {
        float4 v[8];
#pragma unroll
        for (int r = 0; r < 8; r++)
            v[r] = *(const float4*)(xs + (size_t)(rr + r) * D_);
#pragma unroll
        for (int r = 0; r < 8; r++) {
            v[r].x += p.x; v[r].y += p.y; v[r].z += p.z; v[r].w += p.w;
            *(float4*)(os + (size_t)(rr + r) * D_) = v[r];
        }
    }
}

// ---------------- launch ----------------
extern "C" void kernel_launch(void* const* d_in, const int* in_sizes, int n_in,
                              void* d_out, int out_size) {
    const float* x      = (const float*)d_in[0];   // [8,4096,1024]
    const float* active = (const float*)d_in[1];   // [8,256,1024]
    const float* cold   = (const float*)d_in[2];   // [8,1024]
    const float* w_sal  = (const float*)d_in[3];   // [1024]
    const float* w_read = (const float*)d_in[4];   // [1024,1024]

    float* xout       = (float*)d_out;
    float* new_active = xout + (size_t)in_sizes[0];
    float* cold_out   = new_active + (size_t)in_sizes[1];

    { dim3 grid(NSLICE, B_); k_salience<<<grid, 512>>>(x, active, w_sal); }
    k_topk<<<B_, 1024>>>();
    { dim3 grid(GSLICE, B_); k_gather<<<grid, 1024>>>(x, active, new_active); }
    { dim3 grid(D_ / 64, B_); k_ctx<<<grid, 512>>>(cold, cold_out); }
    k_gemv<<<128, 256>>>(w_read);
    { dim3 grid(L_ / 32, B_); k_addproj<<<grid, 256>>>(x, xout); }
}

// round 7
// speedup vs baseline: 1.0128x; 1.0128x over previous
#include <cuda_runtime.h>
#include <cuda_bf16.h>
#include <stdint.h>

#define B_    8
#define L_    4096
#define D_    1024
#define A_    256
#define LC_   4352      // A_ + L_
#define KEEP_ 256
#define NSLICE 34       // salience partial slices (34 * 128 rows = 4352)
#define GSLICE 32       // gather partial slices  (32 * 8 rows = 256)

// -------- scratch (device globals; no allocation allowed) --------
__device__ float g_sal[B_ * LC_];
__device__ float g_part[B_ * NSLICE * D_];   // salience per-block column sums
__device__ float g_kpart[B_ * GSLICE * D_];  // gather per-block kept column sums
__device__ int   g_topidx[B_ * KEEP_];
__device__ float g_ctx[B_ * D_];
__device__ float g_proj[B_ * D_];
__device__ int   g_done[B_];                 // gather arrival counters (reset in k_topk)

// ---------------- K1: salience + per-block partial column sums ----------------
// grid: (NSLICE, B_), block 512 (16 warps). 128 rows/block, 8 rows/warp.
__global__ void k_salience(const float* __restrict__ x,
                           const float* __restrict__ active,
                           const float* __restrict__ wsal) {
    __shared__ float s_col[D_];
    const int b    = blockIdx.y;
    const int tid  = threadIdx.x;
    const int warp = tid >> 5;
    const int lane = tid & 31;

    for (int i = tid; i < D_; i += blockDim.x) s_col[i] = 0.f;

    float4 ws[8];
#pragma unroll
    for (int k = 0; k < 8; k++)
        ws[k] = *(const float4*)(wsal + k * 128 + lane * 4);
    float4 cs[8];
#pragma unroll
    for (int k = 0; k < 8; k++) cs[k] = make_float4(0.f, 0.f, 0.f, 0.f);

    __syncthreads();

    const int row0 = blockIdx.x * 128 + warp * 8;
#pragma unroll
    for (int r = 0; r < 8; r++) {
        const int t = row0 + r;
        const float* src = (t < A_)
            ? active + ((size_t)b * A_ + t) * D_
            : x      + ((size_t)b * L_ + (t - A_)) * D_;
        float dot = 0.f;
#pragma unroll
        for (int k = 0; k < 8; k++) {
            float4 v = *(const float4*)(src + k * 128 + lane * 4);
            dot += v.x * ws[k].x + v.y * ws[k].y + v.z * ws[k].z + v.w * ws[k].w;
            cs[k].x += v.x; cs[k].y += v.y; cs[k].z += v.z; cs[k].w += v.w;
        }
#pragma unroll
        for (int o = 16; o > 0; o >>= 1)
            dot += __shfl_down_sync(0xffffffffu, dot, o);
        if (lane == 0) g_sal[b * LC_ + t] = dot;
    }

#pragma unroll
    for (int k = 0; k < 8; k++) {
        int d0 = k * 128 + lane * 4;
        atomicAdd(&s_col[d0 + 0], cs[k].x);
        atomicAdd(&s_col[d0 + 1], cs[k].y);
        atomicAdd(&s_col[d0 + 2], cs[k].z);
        atomicAdd(&s_col[d0 + 3], cs[k].w);
    }
    __syncthreads();
    float* dst = g_part + ((size_t)b * NSLICE + blockIdx.x) * D_;
    for (int i = tid; i < D_ / 4; i += blockDim.x)
        *(float4*)(dst + i * 4) = *(const float4*)(&s_col[i * 4]);
}

// ---------------- K2: exact top-256 (radix select), sorted ascending ----------------
__device__ __forceinline__ unsigned int order_key(float f) {
    unsigned int u = __float_as_uint(f);
    return u ^ ((u >> 31) ? 0xFFFFFFFFu : 0x80000000u);
}

__global__ void k_topk() {
    const int b    = blockIdx.x;
    const int tid  = threadIdx.x;           // 1024 threads
    const int lane = tid & 31;
    const int warp = tid >> 5;

    __shared__ unsigned int skeys[LC_];
    __shared__ unsigned int hist[256];
    __shared__ int          out_idx[KEEP_];
    __shared__ unsigned int wsum[32];
    __shared__ unsigned int s_prefix;
    __shared__ int          s_krem;

    if (tid == 0) g_done[b] = 0;   // reset gather arrival counter (runs before k_gather)

    for (int i = tid; i < LC_; i += 1024)
        skeys[i] = order_key(g_sal[b * LC_ + i]);
    if (tid == 0) { s_prefix = 0u; s_krem = KEEP_; }
    __syncthreads();

    // 4-pass radix select, bucket scan by warp 0 (shuffle suffix-scan)
    for (int pass = 0; pass < 4; pass++) {
        const int shift = 24 - 8 * pass;
        if (tid < 256) hist[tid] = 0u;
        __syncthreads();
        const unsigned int pfx = s_prefix;
        const int krem = s_krem;
        for (int i = tid; i < LC_; i += 1024) {
            unsigned int k = skeys[i];
            if (pass == 0 || (k >> (shift + 8)) == pfx)
                atomicAdd(&hist[(k >> shift) & 255u], 1u);
        }
        __syncthreads();
        if (warp == 0) {
            unsigned int h[8], suf[8];
            unsigned int acc = 0u;
#pragma unroll
            for (int j = 7; j >= 0; j--) { h[j] = hist[lane * 8 + j]; acc += h[j]; suf[j] = acc; }
            const unsigned int tot = acc;
            unsigned int inc = tot;
#pragma unroll
            for (int off = 1; off < 32; off <<= 1) {
                unsigned int v = __shfl_down_sync(0xffffffffu, inc, off);
                if (lane + off < 32) inc += v;
            }
            const unsigned int after = inc - tot;  // sum over lanes > lane
#pragma unroll
            for (int j = 0; j < 8; j++) {
                unsigned int S  = after + suf[j];
                unsigned int Sn = after + (j < 7 ? suf[j + 1] : 0u);
                if (S >= (unsigned int)krem && Sn < (unsigned int)krem) {
                    s_prefix = (pfx << 8) | (unsigned int)(lane * 8 + j);
                    s_krem   = krem - (int)Sn;
                }
            }
        }
        __syncthreads();
    }

    const unsigned int thr = s_prefix;
    const unsigned int rem = (unsigned int)s_krem;

    // blocked (gt,eq) pair prefix scan; writes kept indices in ascending order
    const int base = tid * 5;                 // 1024*5 = 5120 >= LC_
    unsigned int keys_l[5];
    unsigned int gt = 0u, eq = 0u;
#pragma unroll
    for (int j = 0; j < 5; j++) {
        const int i = base + j;
        unsigned int k = (i < LC_) ? skeys[i] : 0u;
        keys_l[j] = k;
        if (i < LC_) { gt += (k > thr); eq += (k == thr); }
    }
    const unsigned int pair = (gt << 16) | eq;
    unsigned int inc = pair;
#pragma unroll
    for (int off = 1; off < 32; off <<= 1) {
        unsigned int v = __shfl_up_sync(0xffffffffu, inc, off);
        if (lane >= off) inc += v;
    }
    const unsigned int excl = inc - pair;
    if (lane == 31) wsum[warp] = inc;
    __syncthreads();
    if (warp == 0) {
        unsigned int v = wsum[lane];
        unsigned int winc = v;
#pragma unroll
        for (int off = 1; off < 32; off <<= 1) {
            unsigned int t = __shfl_up_sync(0xffffffffu, winc, off);
            if (lane >= off) winc += t;
        }
        wsum[lane] = winc - v;   // exclusive
    }
    __syncthreads();
    const unsigned int basepair = excl + wsum[warp];
    unsigned int gpref = basepair >> 16;
    unsigned int epref = basepair & 0xFFFFu;
#pragma unroll
    for (int j = 0; j < 5; j++) {
        const int i = base + j;
        if (i < LC_) {
            const unsigned int k = keys_l[j];
            if (k > thr) {
                out_idx[gpref + (epref < rem ? epref : rem)] = i;
                gpref++;
            } else if (k == thr) {
                if (epref < rem) out_idx[gpref + epref] = i;
                epref++;
            }
        }
    }
    __syncthreads();
    if (tid < KEEP_) g_topidx[b * KEEP_ + tid] = out_idx[tid];
}

// ---------------- K3: gather kept rows + kept partials + fused ctx (last block/batch) ----------------
// grid: (GSLICE, B_) = (32, B_), block 256 (8 warps); warp w copies row blk*8+w
__global__ void k_gather(const float* __restrict__ x,
                         const float* __restrict__ active,
                         float* __restrict__ new_active_out,
                         const float* __restrict__ cold,
                         float* __restrict__ cold_out) {
    __shared__ float s_col[D_];
    __shared__ int   s_ticket;
    const int b    = blockIdx.y;
    const int tid  = threadIdx.x;
    const int warp = tid >> 5;
    const int lane = tid & 31;
    const int row  = blockIdx.x * 8 + warp;

    for (int i = tid; i < D_; i += blockDim.x) s_col[i] = 0.f;

    const int idx = g_topidx[b * KEEP_ + row];
    const float* src = (idx < A_)
        ? active + ((size_t)b * A_ + idx) * D_
        : x      + ((size_t)b * L_ + (idx - A_)) * D_;
    float* dst = new_active_out + ((size_t)b * KEEP_ + row) * D_;

    float4 v[8];
#pragma unroll
    for (int k = 0; k < 8; k++)
        v[k] = *(const float4*)(src + k * 128 + lane * 4);
    __syncthreads();
#pragma unroll
    for (int k = 0; k < 8; k++) {
        *(float4*)(dst + k * 128 + lane * 4) = v[k];
        int d0 = k * 128 + lane * 4;
        atomicAdd(&s_col[d0 + 0], v[k].x);
        atomicAdd(&s_col[d0 + 1], v[k].y);
        atomicAdd(&s_col[d0 + 2], v[k].z);
        atomicAdd(&s_col[d0 + 3], v[k].w);
    }
    __syncthreads();
    float* kp = g_kpart + ((size_t)b * GSLICE + blockIdx.x) * D_;
    for (int i = tid; i < D_ / 4; i += blockDim.x)
        *(float4*)(kp + i * 4) = *(const float4*)(&s_col[i * 4]);

    // ---- publish partials, elect last block of this batch for the ctx reduction ----
    __threadfence();
    if (tid == 0) s_ticket = atomicAdd(&g_done[b], 1);
    __syncthreads();
    if (s_ticket != GSLICE - 1) return;

    // last block of batch b: reduce 34 salience partials + 32 kept partials
    const int d4 = tid * 4;   // 256 threads x 4 d = 1024
    float4 tot = make_float4(0.f, 0.f, 0.f, 0.f);
    const float* p = g_part + (size_t)b * NSLICE * D_ + d4;
#pragma unroll
    for (int s = 0; s < NSLICE; s++) {
        float4 t = *(const float4*)(p + (size_t)s * D_);
        tot.x += t.x; tot.y += t.y; tot.z += t.z; tot.w += t.w;
    }
    float4 ks = make_float4(0.f, 0.f, 0.f, 0.f);
    const float* kpp = g_kpart + (size_t)b * GSLICE * D_ + d4;
#pragma unroll
    for (int s = 0; s < GSLICE; s++) {
        float4 t = *(const float4*)(kpp + (size_t)s * D_);
        ks.x += t.x; ks.y += t.y; ks.z += t.z; ks.w += t.w;
    }
    const float4 cd = *(const float4*)(cold + b * D_ + d4);
    const float inv_drop = 1.0f / (float)(LC_ - KEEP_);
    const float inv_keep = 1.0f / (float)KEEP_;
    float4 cn, cx;
    cn.x = 0.9f * cd.x + 0.1f * (tot.x - ks.x) * inv_drop;
    cn.y = 0.9f * cd.y + 0.1f * (tot.y - ks.y) * inv_drop;
    cn.z = 0.9f * cd.z + 0.1f * (tot.z - ks.z) * inv_drop;
    cn.w = 0.9f * cd.w + 0.1f * (tot.w - ks.w) * inv_drop;
    cx.x = ks.x * inv_keep + cn.x;
    cx.y = ks.y * inv_keep + cn.y;
    cx.z = ks.z * inv_keep + cn.z;
    cx.w = ks.w * inv_keep + cn.w;
    *(float4*)(cold_out + b * D_ + d4) = cn;
    *(float4*)(g_ctx + b * D_ + d4)    = cx;
}

// ---------------- K5: proj[b,e] = sum_d ctx[b,d] * w_read[e,d] ----------------
// grid 128, block 256 (8 warps, 1 row each)
__global__ void k_gemv(const float* __restrict__ wread) {
    __shared__ float4 sctx[B_ * 256];
    const int tid = threadIdx.x;
    for (int i = tid; i < B_ * 256; i += blockDim.x)
        sctx[i] = *(const float4*)(g_ctx + i * 4);
    __syncthreads();

    const int warp = tid >> 5, lane = tid & 31;
    const int e = blockIdx.x * 8 + warp;
    const float* wr = wread + (size_t)e * D_;
    float acc[B_];
#pragma unroll
    for (int bb = 0; bb < B_; bb++) acc[bb] = 0.f;
#pragma unroll
    for (int k = 0; k < 8; k++) {
        float4 w = *(const float4*)(wr + k * 128 + lane * 4);
#pragma unroll
        for (int bb = 0; bb < B_; bb++) {
            float4 c = sctx[bb * 256 + k * 32 + lane];
            acc[bb] += w.x * c.x + w.y * c.y + w.z * c.z + w.w * c.w;
        }
    }
#pragma unroll
    for (int bb = 0; bb < B_; bb++) {
#pragma unroll
        for (int o = 16; o > 0; o >>= 1)
            acc[bb] += __shfl_down_sync(0xffffffffu, acc[bb], o);
        if (lane == 0) g_proj[bb * D_ + e] = acc[bb];
    }
}

// ---------------- K6: x_out = x + proj (broadcast over l) ----------------
// grid: (L_/32, B_) = (128, B_), block 256; 32 rows per block; MLP-8 prefetch
__global__ void k_addproj(const float* __restrict__ x,
                          float* __restrict__ xout) {
    const int b   = blockIdx.y;
    const int l0  = blockIdx.x * 32;
    const int tid = threadIdx.x;
    const float4 p = *(const float4*)(g_proj + b * D_ + tid * 4);
    const float* xs = x    + ((size_t)b * L_ + l0) * D_ + tid * 4;
    float*       os = xout + ((size_t)b * L_ + l0) * D_ + tid * 4;
#pragma unroll
    for (int rr = 0; rr < 32; rr += 8) {
        float4 v[8];
#pragma unroll
        for (int r = 0; r < 8; r++)
            v[r] = *(const float4*)(xs + (size_t)(rr + r) * D_);
#pragma unroll
        for (int r = 0; r < 8; r++) {
            v[r].x += p.x; v[r].y += p.y; v[r].z += p.z; v[r].w += p.w;
            *(float4*)(os + (size_t)(rr + r) * D_) = v[r];
        }
    }
}

// ---------------- launch ----------------
extern "C" void kernel_launch(void* const* d_in, const int* in_sizes, int n_in,
                              void* d_out, int out_size) {
    const float* x      = (const float*)d_in[0];   // [8,4096,1024]
    const float* active = (const float*)d_in[1];   // [8,256,1024]
    const float* cold   = (const float*)d_in[2];   // [8,1024]
    const float* w_sal  = (const float*)d_in[3];   // [1024]
    const float* w_read = (const float*)d_in[4];   // [1024,1024]

    float* xout       = (float*)d_out;
    float* new_active = xout + (size_t)in_sizes[0];
    float* cold_out   = new_active + (size_t)in_sizes[1];

    { dim3 grid(NSLICE, B_); k_salience<<<grid, 512>>>(x, active, w_sal); }
    k_topk<<<B_, 1024>>>();
    { dim3 grid(GSLICE, B_); k_gather<<<grid, 256>>>(x, active, new_active, cold, cold_out); }
    k_gemv<<<128, 256>>>(w_read);
    { dim3 grid(L_ / 32, B_); k_addproj<<<grid, 256>>>(x, xout); }
}

// round 8
// speedup vs baseline: 1.0195x; 1.0066x over previous
#include <cuda_runtime.h>
#include <cuda_bf16.h>
#include <stdint.h>

#define B_    8
#define L_    4096
#define D_    1024
#define A_    256
#define LC_   4352      // A_ + L_
#define KEEP_ 256
#define NSLICE 34       // salience partial slices (34 * 128 rows = 4352)
#define GSLICE 32       // gather partial slices  (32 * 8 rows = 256)

// -------- scratch (device globals; no allocation allowed) --------
__device__ float g_sal[B_ * LC_];
__device__ float g_part[B_ * NSLICE * D_];   // salience per-block column sums
__device__ float g_kpart[B_ * GSLICE * D_];  // gather per-block kept column sums
__device__ int   g_topidx[B_ * KEEP_];
__device__ float g_ctx[B_ * D_];
__device__ float g_proj[B_ * D_];

// ---------------- K1: salience + per-block partial column sums ----------------
// grid: (NSLICE, B_), block 512 (16 warps). 128 rows/block, 8 rows/warp.
__global__ void k_salience(const float* __restrict__ x,
                           const float* __restrict__ active,
                           const float* __restrict__ wsal) {
    __shared__ float s_col[D_];
    const int b    = blockIdx.y;
    const int tid  = threadIdx.x;
    const int warp = tid >> 5;
    const int lane = tid & 31;

    for (int i = tid; i < D_; i += blockDim.x) s_col[i] = 0.f;

    float4 ws[8];
#pragma unroll
    for (int k = 0; k < 8; k++)
        ws[k] = *(const float4*)(wsal + k * 128 + lane * 4);
    float4 cs[8];
#pragma unroll
    for (int k = 0; k < 8; k++) cs[k] = make_float4(0.f, 0.f, 0.f, 0.f);

    __syncthreads();

    const int row0 = blockIdx.x * 128 + warp * 8;
#pragma unroll
    for (int r = 0; r < 8; r++) {
        const int t = row0 + r;
        const float* src = (t < A_)
            ? active + ((size_t)b * A_ + t) * D_
            : x      + ((size_t)b * L_ + (t - A_)) * D_;
        float dot = 0.f;
#pragma unroll
        for (int k = 0; k < 8; k++) {
            float4 v = *(const float4*)(src + k * 128 + lane * 4);
            dot += v.x * ws[k].x + v.y * ws[k].y + v.z * ws[k].z + v.w * ws[k].w;
            cs[k].x += v.x; cs[k].y += v.y; cs[k].z += v.z; cs[k].w += v.w;
        }
#pragma unroll
        for (int o = 16; o > 0; o >>= 1)
            dot += __shfl_down_sync(0xffffffffu, dot, o);
        if (lane == 0) g_sal[b * LC_ + t] = dot;
    }

#pragma unroll
    for (int k = 0; k < 8; k++) {
        int d0 = k * 128 + lane * 4;
        atomicAdd(&s_col[d0 + 0], cs[k].x);
        atomicAdd(&s_col[d0 + 1], cs[k].y);
        atomicAdd(&s_col[d0 + 2], cs[k].z);
        atomicAdd(&s_col[d0 + 3], cs[k].w);
    }
    __syncthreads();
    float* dst = g_part + ((size_t)b * NSLICE + blockIdx.x) * D_;
    for (int i = tid; i < D_ / 4; i += blockDim.x)
        *(float4*)(dst + i * 4) = *(const float4*)(&s_col[i * 4]);
}

// ---------------- K2: exact top-256 (radix select), sorted ascending ----------------
__device__ __forceinline__ unsigned int order_key(float f) {
    unsigned int u = __float_as_uint(f);
    return u ^ ((u >> 31) ? 0xFFFFFFFFu : 0x80000000u);
}

__global__ void k_topk() {
    const int b    = blockIdx.x;
    const int tid  = threadIdx.x;           // 1024 threads
    const int lane = tid & 31;
    const int warp = tid >> 5;

    __shared__ unsigned int skeys[LC_];
    __shared__ unsigned int hist[256];
    __shared__ int          out_idx[KEEP_];
    __shared__ unsigned int wsum[32];
    __shared__ unsigned int s_prefix;
    __shared__ int          s_krem;

    for (int i = tid; i < LC_; i += 1024)
        skeys[i] = order_key(g_sal[b * LC_ + i]);
    if (tid == 0) { s_prefix = 0u; s_krem = KEEP_; }
    __syncthreads();

    // 4-pass radix select, bucket scan by warp 0 (shuffle suffix-scan)
    for (int pass = 0; pass < 4; pass++) {
        const int shift = 24 - 8 * pass;
        if (tid < 256) hist[tid] = 0u;
        __syncthreads();
        const unsigned int pfx = s_prefix;
        const int krem = s_krem;
        for (int i = tid; i < LC_; i += 1024) {
            unsigned int k = skeys[i];
            if (pass == 0 || (k >> (shift + 8)) == pfx)
                atomicAdd(&hist[(k >> shift) & 255u], 1u);
        }
        __syncthreads();
        if (warp == 0) {
            unsigned int h[8], suf[8];
            unsigned int acc = 0u;
#pragma unroll
            for (int j = 7; j >= 0; j--) { h[j] = hist[lane * 8 + j]; acc += h[j]; suf[j] = acc; }
            const unsigned int tot = acc;
            unsigned int inc = tot;
#pragma unroll
            for (int off = 1; off < 32; off <<= 1) {
                unsigned int v = __shfl_down_sync(0xffffffffu, inc, off);
                if (lane + off < 32) inc += v;
            }
            const unsigned int after = inc - tot;  // sum over lanes > lane
#pragma unroll
            for (int j = 0; j < 8; j++) {
                unsigned int S  = after + suf[j];
                unsigned int Sn = after + (j < 7 ? suf[j + 1] : 0u);
                if (S >= (unsigned int)krem && Sn < (unsigned int)krem) {
                    s_prefix = (pfx << 8) | (unsigned int)(lane * 8 + j);
                    s_krem   = krem - (int)Sn;
                }
            }
        }
        __syncthreads();
    }

    const unsigned int thr = s_prefix;
    const unsigned int rem = (unsigned int)s_krem;

    // blocked (gt,eq) pair prefix scan; writes kept indices in ascending order
    const int base = tid * 5;                 // 1024*5 = 5120 >= LC_
    unsigned int keys_l[5];
    unsigned int gt = 0u, eq = 0u;
#pragma unroll
    for (int j = 0; j < 5; j++) {
        const int i = base + j;
        unsigned int k = (i < LC_) ? skeys[i] : 0u;
        keys_l[j] = k;
        if (i < LC_) { gt += (k > thr); eq += (k == thr); }
    }
    const unsigned int pair = (gt << 16) | eq;
    unsigned int inc = pair;
#pragma unroll
    for (int off = 1; off < 32; off <<= 1) {
        unsigned int v = __shfl_up_sync(0xffffffffu, inc, off);
        if (lane >= off) inc += v;
    }
    const unsigned int excl = inc - pair;
    if (lane == 31) wsum[warp] = inc;
    __syncthreads();
    if (warp == 0) {
        unsigned int v = wsum[lane];
        unsigned int winc = v;
#pragma unroll
        for (int off = 1; off < 32; off <<= 1) {
            unsigned int t = __shfl_up_sync(0xffffffffu, winc, off);
            if (lane >= off) winc += t;
        }
        wsum[lane] = winc - v;   // exclusive
    }
    __syncthreads();
    const unsigned int basepair = excl + wsum[warp];
    unsigned int gpref = basepair >> 16;
    unsigned int epref = basepair & 0xFFFFu;
#pragma unroll
    for (int j = 0; j < 5; j++) {
        const int i = base + j;
        if (i < LC_) {
            const unsigned int k = keys_l[j];
            if (k > thr) {
                out_idx[gpref + (epref < rem ? epref : rem)] = i;
                gpref++;
            } else if (k == thr) {
                if (epref < rem) out_idx[gpref + epref] = i;
                epref++;
            }
        }
    }
    __syncthreads();
    if (tid < KEEP_) g_topidx[b * KEEP_ + tid] = out_idx[tid];
}

// ---------------- K3: gather kept rows + per-block kept column sums ----------------
// grid: (GSLICE, B_) = (32, B_), block 256 (8 warps); warp w copies row blk*8+w
__global__ void k_gather(const float* __restrict__ x,
                         const float* __restrict__ active,
                         float* __restrict__ new_active_out) {
    __shared__ float s_col[D_];
    const int b    = blockIdx.y;
    const int tid  = threadIdx.x;
    const int warp = tid >> 5;
    const int lane = tid & 31;
    const int row  = blockIdx.x * 8 + warp;

    for (int i = tid; i < D_; i += blockDim.x) s_col[i] = 0.f;

    const int idx = g_topidx[b * KEEP_ + row];
    const float* src = (idx < A_)
        ? active + ((size_t)b * A_ + idx) * D_
        : x      + ((size_t)b * L_ + (idx - A_)) * D_;
    float* dst = new_active_out + ((size_t)b * KEEP_ + row) * D_;

    float4 v[8];
#pragma unroll
    for (int k = 0; k < 8; k++)
        v[k] = *(const float4*)(src + k * 128 + lane * 4);
    __syncthreads();
#pragma unroll
    for (int k = 0; k < 8; k++) {
        *(float4*)(dst + k * 128 + lane * 4) = v[k];
        int d0 = k * 128 + lane * 4;
        atomicAdd(&s_col[d0 + 0], v[k].x);
        atomicAdd(&s_col[d0 + 1], v[k].y);
        atomicAdd(&s_col[d0 + 2], v[k].z);
        atomicAdd(&s_col[d0 + 3], v[k].w);
    }
    __syncthreads();
    float* kp = g_kpart + ((size_t)b * GSLICE + blockIdx.x) * D_;
    for (int i = tid; i < D_ / 4; i += blockDim.x)
        *(float4*)(kp + i * 4) = *(const float4*)(&s_col[i * 4]);
}

// ---------------- K4: reduce partials -> cold_new + ctx ----------------
// grid (D_/64, B_) = (16, B_), block 512: 8 threads cooperate per d (64 d per block)
__global__ void k_ctx(const float* __restrict__ cold,
                      float* __restrict__ cold_out) {
    __shared__ float st[8][64];
    __shared__ float sk[8][64];
    const int b  = blockIdx.y;
    const int d0 = blockIdx.x * 64;
    const int dx = threadIdx.x & 63;
    const int sy = threadIdx.x >> 6;

    float tot = 0.f;
    const float* p = g_part + (size_t)b * NSLICE * D_ + d0 + dx;
#pragma unroll
    for (int s = sy; s < NSLICE; s += 8) tot += p[(size_t)s * D_];

    float ks = 0.f;
    const float* kp = g_kpart + (size_t)b * GSLICE * D_ + d0 + dx;
#pragma unroll
    for (int s = sy; s < GSLICE; s += 8) ks += kp[(size_t)s * D_];

    st[sy][dx] = tot;
    sk[sy][dx] = ks;
    __syncthreads();
    if (sy == 0) {
        float t = 0.f, k = 0.f;
#pragma unroll
        for (int s = 0; s < 8; s++) { t += st[s][dx]; k += sk[s][dx]; }
        const int i = b * D_ + d0 + dx;
        const float dropped_mean = (t - k) * (1.0f / (float)(LC_ - KEEP_));
        const float cn = 0.9f * cold[i] + 0.1f * dropped_mean;
        cold_out[i] = cn;
        g_ctx[i] = k * (1.0f / (float)KEEP_) + cn;
    }
}

// ---------------- K5: proj[b,e] = sum_d ctx[b,d] * w_read[e,d] ----------------
// grid 256, block 128 (4 warps, 1 e-row each); full row front-batched into regs
__global__ void k_gemv(const float* __restrict__ wread) {
    __shared__ float4 sctx[B_ * 256];   // 32 KB: ctx for all 8 batches
    const int tid = threadIdx.x;
#pragma unroll
    for (int i = tid; i < B_ * 256; i += 128)
        sctx[i] = *(const float4*)(g_ctx + i * 4);

    const int warp = tid >> 5, lane = tid & 31;
    const int e = blockIdx.x * 4 + warp;
    const float* wr = wread + (size_t)e * D_ + lane * 4;

    // front-batch the whole 4KB row: 8 independent LDG.128 per thread (MLP=8)
    float4 w[8];
#pragma unroll
    for (int k = 0; k < 8; k++)
        w[k] = *(const float4*)(wr + k * 128);

    __syncthreads();

    float acc[B_];
#pragma unroll
    for (int bb = 0; bb < B_; bb++) acc[bb] = 0.f;
#pragma unroll
    for (int k = 0; k < 8; k++) {
#pragma unroll
        for (int bb = 0; bb < B_; bb++) {
            float4 c = sctx[bb * 256 + k * 32 + lane];
            acc[bb] += w[k].x * c.x + w[k].y * c.y + w[k].z * c.z + w[k].w * c.w;
        }
    }
#pragma unroll
    for (int bb = 0; bb < B_; bb++) {
#pragma unroll
        for (int o = 16; o > 0; o >>= 1)
            acc[bb] += __shfl_down_sync(0xffffffffu, acc[bb], o);
        if (lane == 0) g_proj[bb * D_ + e] = acc[bb];
    }
}

// ---------------- K6: x_out = x + proj (broadcast over l) ----------------
// grid: (L_/32, B_) = (128, B_), block 256; 32 rows per block; MLP-8 prefetch
__global__ void k_addproj(const float* __restrict__ x,
                          float* __restrict__ xout) {
    const int b   = blockIdx.y;
    const int l0  = blockIdx.x * 32;
    const int tid = threadIdx.x;
    const float4 p = *(const float4*)(g_proj + b * D_ + tid * 4);
    const float* xs = x    + ((size_t)b * L_ + l0) * D_ + tid * 4;
    float*       os = xout + ((size_t)b * L_ + l0) * D_ + tid * 4;
#pragma unroll
    for (int rr = 0; rr < 32; rr += 8) {
        float4 v[8];
#pragma unroll
        for (int r = 0; r < 8; r++)
            v[r] = *(const float4*)(xs + (size_t)(rr + r) * D_);
#pragma unroll
        for (int r = 0; r < 8; r++) {
            v[r].x += p.x; v[r].y += p.y; v[r].z += p.z; v[r].w += p.w;
            *(float4*)(os + (size_t)(rr + r) * D_) = v[r];
        }
    }
}

// ---------------- launch ----------------
extern "C" void kernel_launch(void* const* d_in, const int* in_sizes, int n_in,
                              void* d_out, int out_size) {
    const float* x      = (const float*)d_in[0];   // [8,4096,1024]
    const float* active = (const float*)d_in[1];   // [8,256,1024]
    const float* cold   = (const float*)d_in[2];   // [8,1024]
    const float* w_sal  = (const float*)d_in[3];   // [1024]
    const float* w_read = (const float*)d_in[4];   // [1024,1024]

    float* xout       = (float*)d_out;
    float* new_active = xout + (size_t)in_sizes[0];
    float* cold_out   = new_active + (size_t)in_sizes[1];

    { dim3 grid(NSLICE, B_); k_salience<<<grid, 512>>>(x, active, w_sal); }
    k_topk<<<B_, 1024>>>();
    { dim3 grid(GSLICE, B_); k_gather<<<grid, 256>>>(x, active, new_active); }
    { dim3 grid(D_ / 64, B_); k_ctx<<<grid, 512>>>(cold, cold_out); }
    k_gemv<<<256, 128>>>(w_read);
    { dim3 grid(L_ / 32, B_); k_addproj<<<grid, 256>>>(x, xout); }
}

// round 10
// speedup vs baseline: 1.0235x; 1.0039x over previous
#include <cuda_runtime.h>
#include <cuda_bf16.h>
#include <stdint.h>

#define B_    8
#define L_    4096
#define D_    1024
#define A_    256
#define LC_   4352      // A_ + L_
#define KEEP_ 256
#define NSLICE 34       // salience partial slices (34 * 128 rows = 4352)
#define GSLICE 32       // gather partial slices  (32 * 8 rows = 256)

// -------- scratch (device globals; no allocation allowed) --------
__device__ float g_sal[B_ * LC_];
__device__ float g_part[B_ * NSLICE * D_];   // salience per-block column sums
__device__ float g_kpart[B_ * GSLICE * D_];  // gather per-block kept column sums
__device__ int   g_topidx[B_ * KEEP_];
__device__ float g_ctx[B_ * D_];
__device__ float g_proj[B_ * D_];
__device__ int   g_ctx_flag;                 // release/acquire flag (reset in k_gather)
__device__ float g_scratch[16];              // prefetch sink

// ---------------- K1: salience + per-block partial column sums ----------------
// grid: (NSLICE, B_), block 512 (16 warps). 128 rows/block, 8 rows/warp.
__global__ void k_salience(const float* __restrict__ x,
                           const float* __restrict__ active,
                           const float* __restrict__ wsal) {
    __shared__ float s_col[D_];
    const int b    = blockIdx.y;
    const int tid  = threadIdx.x;
    const int warp = tid >> 5;
    const int lane = tid & 31;

    for (int i = tid; i < D_; i += blockDim.x) s_col[i] = 0.f;

    float4 ws[8];
#pragma unroll
    for (int k = 0; k < 8; k++)
        ws[k] = *(const float4*)(wsal + k * 128 + lane * 4);
    float4 cs[8];
#pragma unroll
    for (int k = 0; k < 8; k++) cs[k] = make_float4(0.f, 0.f, 0.f, 0.f);

    __syncthreads();

    const int row0 = blockIdx.x * 128 + warp * 8;
#pragma unroll
    for (int r = 0; r < 8; r++) {
        const int t = row0 + r;
        const float* src = (t < A_)
            ? active + ((size_t)b * A_ + t) * D_
            : x      + ((size_t)b * L_ + (t - A_)) * D_;
        float dot = 0.f;
#pragma unroll
        for (int k = 0; k < 8; k++) {
            float4 v = *(const float4*)(src + k * 128 + lane * 4);
            dot += v.x * ws[k].x + v.y * ws[k].y + v.z * ws[k].z + v.w * ws[k].w;
            cs[k].x += v.x; cs[k].y += v.y; cs[k].z += v.z; cs[k].w += v.w;
        }
#pragma unroll
        for (int o = 16; o > 0; o >>= 1)
            dot += __shfl_down_sync(0xffffffffu, dot, o);
        if (lane == 0) g_sal[b * LC_ + t] = dot;
    }

#pragma unroll
    for (int k = 0; k < 8; k++) {
        int d0 = k * 128 + lane * 4;
        atomicAdd(&s_col[d0 + 0], cs[k].x);
        atomicAdd(&s_col[d0 + 1], cs[k].y);
        atomicAdd(&s_col[d0 + 2], cs[k].z);
        atomicAdd(&s_col[d0 + 3], cs[k].w);
    }
    __syncthreads();
    float* dst = g_part + ((size_t)b * NSLICE + blockIdx.x) * D_;
    for (int i = tid; i < D_ / 4; i += blockDim.x)
        *(float4*)(dst + i * 4) = *(const float4*)(&s_col[i * 4]);
}

// ---------------- K2: top-256 radix select (blocks 0..7) + w_read L2 prefetch (blocks 8..15) ----------------
__device__ __forceinline__ unsigned int order_key(float f) {
    unsigned int u = __float_as_uint(f);
    return u ^ ((u >> 31) ? 0xFFFFFFFFu : 0x80000000u);
}

__global__ void k_topk(const float* __restrict__ wread) {
    const int blk  = blockIdx.x;
    const int tid  = threadIdx.x;           // 1024 threads
    const int lane = tid & 31;
    const int warp = tid >> 5;

    if (blk >= B_) {
        // prefetch role: stream 512KB of w_read through L2
        const int pb = blk - B_;            // 0..7
        const float4* src = (const float4*)(wread) + (size_t)pb * 32768 + tid;
        float4 s = make_float4(0.f, 0.f, 0.f, 0.f);
#pragma unroll
        for (int k = 0; k < 32; k++) {
            float4 v = src[(size_t)k * 1024];
            s.x += v.x; s.y += v.y; s.z += v.z; s.w += v.w;
        }
        float sum = s.x + s.y + s.z + s.w;
#pragma unroll
        for (int o = 16; o > 0; o >>= 1)
            sum += __shfl_down_sync(0xffffffffu, sum, o);
        if (tid == 0) g_scratch[pb] = sum;   // deterministic sink
        return;
    }
    const int b = blk;

    __shared__ unsigned int skeys[LC_];
    __shared__ unsigned int hist[256];
    __shared__ int          out_idx[KEEP_];
    __shared__ unsigned int wsum[32];
    __shared__ unsigned int s_prefix;
    __shared__ int          s_krem;

    for (int i = tid; i < LC_; i += 1024)
        skeys[i] = order_key(g_sal[b * LC_ + i]);
    if (tid == 0) { s_prefix = 0u; s_krem = KEEP_; }
    __syncthreads();

    for (int pass = 0; pass < 4; pass++) {
        const int shift = 24 - 8 * pass;
        if (tid < 256) hist[tid] = 0u;
        __syncthreads();
        const unsigned int pfx = s_prefix;
        const int krem = s_krem;
        for (int i = tid; i < LC_; i += 1024) {
            unsigned int k = skeys[i];
            if (pass == 0 || (k >> (shift + 8)) == pfx)
                atomicAdd(&hist[(k >> shift) & 255u], 1u);
        }
        __syncthreads();
        if (warp == 0) {
            unsigned int h[8], suf[8];
            unsigned int acc = 0u;
#pragma unroll
            for (int j = 7; j >= 0; j--) { h[j] = hist[lane * 8 + j]; acc += h[j]; suf[j] = acc; }
            const unsigned int tot = acc;
            unsigned int inc = tot;
#pragma unroll
            for (int off = 1; off < 32; off <<= 1) {
                unsigned int v = __shfl_down_sync(0xffffffffu, inc, off);
                if (lane + off < 32) inc += v;
            }
            const unsigned int after = inc - tot;
#pragma unroll
            for (int j = 0; j < 8; j++) {
                unsigned int S  = after + suf[j];
                unsigned int Sn = after + (j < 7 ? suf[j + 1] : 0u);
                if (S >= (unsigned int)krem && Sn < (unsigned int)krem) {
                    s_prefix = (pfx << 8) | (unsigned int)(lane * 8 + j);
                    s_krem   = krem - (int)Sn;
                }
            }
        }
        __syncthreads();
    }

    const unsigned int thr = s_prefix;
    const unsigned int rem = (unsigned int)s_krem;

    const int base = tid * 5;                 // 1024*5 = 5120 >= LC_
    unsigned int keys_l[5];
    unsigned int gt = 0u, eq = 0u;
#pragma unroll
    for (int j = 0; j < 5; j++) {
        const int i = base + j;
        unsigned int k = (i < LC_) ? skeys[i] : 0u;
        keys_l[j] = k;
        if (i < LC_) { gt += (k > thr); eq += (k == thr); }
    }
    const unsigned int pair = (gt << 16) | eq;
    unsigned int inc = pair;
#pragma unroll
    for (int off = 1; off < 32; off <<= 1) {
        unsigned int v = __shfl_up_sync(0xffffffffu, inc, off);
        if (lane >= off) inc += v;
    }
    const unsigned int excl = inc - pair;
    if (lane == 31) wsum[warp] = inc;
    __syncthreads();
    if (warp == 0) {
        unsigned int v = wsum[lane];
        unsigned int winc = v;
#pragma unroll
        for (int off = 1; off < 32; off <<= 1) {
            unsigned int t = __shfl_up_sync(0xffffffffu, winc, off);
            if (lane >= off) winc += t;
        }
        wsum[lane] = winc - v;
    }
    __syncthreads();
    const unsigned int basepair = excl + wsum[warp];
    unsigned int gpref = basepair >> 16;
    unsigned int epref = basepair & 0xFFFFu;
#pragma unroll
    for (int j = 0; j < 5; j++) {
        const int i = base + j;
        if (i < LC_) {
            const unsigned int k = keys_l[j];
            if (k > thr) {
                out_idx[gpref + (epref < rem ? epref : rem)] = i;
                gpref++;
            } else if (k == thr) {
                if (epref < rem) out_idx[gpref + epref] = i;
                epref++;
            }
        }
    }
    __syncthreads();
    if (tid < KEEP_) g_topidx[b * KEEP_ + tid] = out_idx[tid];
}

// ---------------- K3: gather kept rows + per-block kept column sums ----------------
// grid: (GSLICE, B_) = (32, B_), block 256 (8 warps); also resets g_ctx_flag
__global__ void k_gather(const float* __restrict__ x,
                         const float* __restrict__ active,
                         float* __restrict__ new_active_out) {
    __shared__ float s_col[D_];
    const int b    = blockIdx.y;
    const int tid  = threadIdx.x;
    const int warp = tid >> 5;
    const int lane = tid & 31;
    const int row  = blockIdx.x * 8 + warp;

    if (blockIdx.x == 0 && blockIdx.y == 0 && tid == 0) g_ctx_flag = 0;

    for (int i = tid; i < D_; i += blockDim.x) s_col[i] = 0.f;

    const int idx = g_topidx[b * KEEP_ + row];
    const float* src = (idx < A_)
        ? active + ((size_t)b * A_ + idx) * D_
        : x      + ((size_t)b * L_ + (idx - A_)) * D_;
    float* dst = new_active_out + ((size_t)b * KEEP_ + row) * D_;

    float4 v[8];
#pragma unroll
    for (int k = 0; k < 8; k++)
        v[k] = *(const float4*)(src + k * 128 + lane * 4);
    __syncthreads();
#pragma unroll
    for (int k = 0; k < 8; k++) {
        *(float4*)(dst + k * 128 + lane * 4) = v[k];
        int d0 = k * 128 + lane * 4;
        atomicAdd(&s_col[d0 + 0], v[k].x);
        atomicAdd(&s_col[d0 + 1], v[k].y);
        atomicAdd(&s_col[d0 + 2], v[k].z);
        atomicAdd(&s_col[d0 + 3], v[k].w);
    }
    __syncthreads();
    float* kp = g_kpart + ((size_t)b * GSLICE + blockIdx.x) * D_;
    for (int i = tid; i < D_ / 4; i += blockDim.x)
        *(float4*)(kp + i * 4) = *(const float4*)(&s_col[i * 4]);
}

// ---------------- K4: fused ctx (blocks 0..7) + gemv (blocks 8..135), one launch ----------------
// block = 256 threads. ctx role: one block per batch, reduce partials -> cold_new/g_ctx,
// release via flag. gemv role: front-batch w row loads (DRAM/L2), spin-acquire, FMA.
__global__ void k_ctxgemv(const float* __restrict__ cold,
                          float* __restrict__ cold_out,
                          const float* __restrict__ wread) {
    const int tid = threadIdx.x;

    if (blockIdx.x < B_) {
        // ---- ctx role ----
        const int b  = blockIdx.x;
        const int d4 = tid * 4;
        float4 tot = make_float4(0.f, 0.f, 0.f, 0.f);
        const float* p = g_part + (size_t)b * NSLICE * D_ + d4;
#pragma unroll
        for (int s = 0; s < NSLICE; s++) {
            float4 t = *(const float4*)(p + (size_t)s * D_);
            tot.x += t.x; tot.y += t.y; tot.z += t.z; tot.w += t.w;
        }
        float4 ks = make_float4(0.f, 0.f, 0.f, 0.f);
        const float* kpp = g_kpart + (size_t)b * GSLICE * D_ + d4;
#pragma unroll
        for (int s = 0; s < GSLICE; s++) {
            float4 t = *(const float4*)(kpp + (size_t)s * D_);
            ks.x += t.x; ks.y += t.y; ks.z += t.z; ks.w += t.w;
        }
        const float4 cd = *(const float4*)(cold + b * D_ + d4);
        const float inv_drop = 1.0f / (float)(LC_ - KEEP_);
        const float inv_keep = 1.0f / (float)KEEP_;
        float4 cn, cx;
        cn.x = 0.9f * cd.x + 0.1f * (tot.x - ks.x) * inv_drop;
        cn.y = 0.9f * cd.y + 0.1f * (tot.y - ks.y) * inv_drop;
        cn.z = 0.9f * cd.z + 0.1f * (tot.z - ks.z) * inv_drop;
        cn.w = 0.9f * cd.w + 0.1f * (tot.w - ks.w) * inv_drop;
        cx.x = ks.x * inv_keep + cn.x;
        cx.y = ks.y * inv_keep + cn.y;
        cx.z = ks.z * inv_keep + cn.z;
        cx.w = ks.w * inv_keep + cn.w;
        *(float4*)(cold_out + b * D_ + d4) = cn;
        *(float4*)(g_ctx + b * D_ + d4)    = cx;
        __threadfence();
        __syncthreads();
        if (tid == 0) atomicAdd(&g_ctx_flag, 1);   // release
        return;
    }

    // ---- gemv role ----
    __shared__ float4 sctx[B_ * 256];   // 32 KB
    const int gid  = blockIdx.x - B_;   // 0..127
    const int warp = tid >> 5, lane = tid & 31;
    const int e = gid * 8 + warp;
    const float* wr = wread + (size_t)e * D_ + lane * 4;

    // front-batch the whole 4KB row (MLP=8) BEFORE waiting for ctx
    float4 w[8];
#pragma unroll
    for (int k = 0; k < 8; k++)
        w[k] = *(const float4*)(wr + k * 128);

    // acquire: wait for all 8 ctx blocks
    if (tid == 0) {
        while (atomicAdd(&g_ctx_flag, 0) < B_) { __nanosleep(64); }
    }
    __syncthreads();
    __threadfence();

    for (int i = tid; i < B_ * 256; i += 256)
        sctx[i] = *(const float4*)(g_ctx + i * 4);
    __syncthreads();

    float acc[B_];
#pragma unroll
    for (int bb = 0; bb < B_; bb++) acc[bb] = 0.f;
#pragma unroll
    for (int k = 0; k < 8; k++) {
#pragma unroll
        for (int bb = 0; bb < B_; bb++) {
            float4 c = sctx[bb * 256 + k * 32 + lane];
            acc[bb] += w[k].x * c.x + w[k].y * c.y + w[k].z * c.z + w[k].w * c.w;
        }
    }
#pragma unroll
    for (int bb = 0; bb < B_; bb++) {
#pragma unroll
        for (int o = 16; o > 0; o >>= 1)
            acc[bb] += __shfl_down_sync(0xffffffffu, acc[bb], o);
        if (lane == 0) g_proj[bb * D_ + e] = acc[bb];
    }
}

// ---------------- K6: x_out = x + proj (broadcast over l) ----------------
// grid: (L_/32, B_) = (128, B_), block 256; 32 rows per block; MLP-8 prefetch
__global__ void k_addproj(const float* __restrict__ x,
                          float* __restrict__ xout) {
    const int b   = blockIdx.y;
    const int l0  = blockIdx.x * 32;
    const int tid = threadIdx.x;
    const float4 p = *(const float4*)(g_proj + b * D_ + tid * 4);
    const float* xs = x    + ((size_t)b * L_ + l0) * D_ + tid * 4;
    float*       os = xout + ((size_t)b * L_ + l0) * D_ + tid * 4;
#pragma unroll
    for (int rr = 0; rr < 32; rr += 8) {
        float4 v[8];
#pragma unroll
        for (int r = 0; r < 8; r++)
            v[r] = *(const float4*)(xs + (size_t)(rr + r) * D_);
#pragma unroll
        for (int r = 0; r < 8; r++) {
            v[r].x += p.x; v[r].y += p.y; v[r].z += p.z; v[r].w += p.w;
            *(float4*)(os + (size_t)(rr + r) * D_) = v[r];
        }
    }
}

// ---------------- launch ----------------
extern "C" void kernel_launch(void* const* d_in, const int* in_sizes, int n_in,
                              void* d_out, int out_size) {
    const float* x      = (const float*)d_in[0];   // [8,4096,1024]
    const float* active = (const float*)d_in[1];   // [8,256,1024]
    const float* cold   = (const float*)d_in[2];   // [8,1024]
    const float* w_sal  = (const float*)d_in[3];   // [1024]
    const float* w_read = (const float*)d_in[4];   // [1024,1024]

    float* xout       = (float*)d_out;
    float* new_active = xout + (size_t)in_sizes[0];
    float* cold_out   = new_active + (size_t)in_sizes[1];

    { dim3 grid(NSLICE, B_); k_salience<<<grid, 512>>>(x, active, w_sal); }
    k_topk<<<B_ + 8, 1024>>>(w_read);                 // topk + w_read L2 prefetch
    { dim3 grid(GSLICE, B_); k_gather<<<grid, 256>>>(x, active, new_active); }
    k_ctxgemv<<<B_ + 128, 256>>>(cold, cold_out, w_read);
    { dim3 grid(L_ / 32, B_); k_addproj<<<grid, 256>>>(x, xout); }
}

// round 11
// speedup vs baseline: 1.1048x; 1.0794x over previous
#include <cuda_runtime.h>
#include <cuda_bf16.h>
#include <stdint.h>

#define B_    8
#define L_    4096
#define D_    1024
#define A_    256
#define LC_   4352      // A_ + L_
#define KEEP_ 256
#define GRID_ 144       // <= SM count; one block per SM guaranteed
#define TPB_  512
#define BPB_  18        // blocks per batch (144/8)
#define NSLICE 18
#define GSLICE 18
#define SROWS 242       // ceil(4352/18)
#define GROWS 15        // ceil(256/18)

// -------- scratch (device globals; no allocation allowed) --------
__device__ unsigned g_barrier[8];
__device__ float g_sal[B_ * LC_];
__device__ float g_part[B_ * NSLICE * D_];
__device__ float g_kpart[B_ * GSLICE * D_];
__device__ int   g_topidx[B_ * KEEP_];
__device__ float g_ctx[B_ * D_];
__device__ float g_proj[B_ * D_];

__global__ void k_init() {
    if (threadIdx.x < 8) g_barrier[threadIdx.x] = 0u;
}

__device__ __forceinline__ void gbar(int ph) {
    __syncthreads();
    __threadfence();
    if (threadIdx.x == 0) {
        atomicAdd(&g_barrier[ph], 1u);
        while (atomicAdd(&g_barrier[ph], 0u) < (unsigned)GRID_) __nanosleep(128);
        __threadfence();
    }
    __syncthreads();
}

__device__ __forceinline__ unsigned int order_key(float f) {
    unsigned int u = __float_as_uint(f);
    return u ^ ((u >> 31) ? 0xFFFFFFFFu : 0x80000000u);
}

__global__ void __launch_bounds__(TPB_, 1)
k_fused(const float* __restrict__ x,
        const float* __restrict__ active,
        const float* __restrict__ cold,
        const float* __restrict__ wsal,
        const float* __restrict__ wread,
        float* __restrict__ xout,
        float* __restrict__ new_active,
        float* __restrict__ cold_out) {
    __shared__ __align__(16) char smem_raw[33024];   // max phase need: 32KB (gemv sctx)
    __shared__ unsigned s_prefix;
    __shared__ int s_krem;

    const int blk  = blockIdx.x;
    const int tid  = threadIdx.x;
    const int warp = tid >> 5;
    const int lane = tid & 31;

    //================ P0: salience + per-block partial column sums ================
    {
        float* s_col = (float*)smem_raw;
        const int b  = blk / BPB_;
        const int sl = blk % BPB_;
        for (int i = tid; i < D_; i += TPB_) s_col[i] = 0.f;

        float4 ws[8];
#pragma unroll
        for (int k = 0; k < 8; k++)
            ws[k] = *(const float4*)(wsal + k * 128 + lane * 4);
        float4 cs[8];
#pragma unroll
        for (int k = 0; k < 8; k++) cs[k] = make_float4(0.f, 0.f, 0.f, 0.f);
        __syncthreads();

        const int row0   = sl * SROWS;
        const int rowend = min(LC_, row0 + SROWS);
        for (int t = row0 + warp; t < rowend; t += 16) {
            const float* src = (t < A_)
                ? active + ((size_t)b * A_ + t) * D_
                : x      + ((size_t)b * L_ + (t - A_)) * D_;
            float dot = 0.f;
#pragma unroll
            for (int k = 0; k < 8; k++) {
                float4 v = *(const float4*)(src + k * 128 + lane * 4);
                dot += v.x * ws[k].x + v.y * ws[k].y + v.z * ws[k].z + v.w * ws[k].w;
                cs[k].x += v.x; cs[k].y += v.y; cs[k].z += v.z; cs[k].w += v.w;
            }
#pragma unroll
            for (int o = 16; o > 0; o >>= 1)
                dot += __shfl_down_sync(0xffffffffu, dot, o);
            if (lane == 0) g_sal[b * LC_ + t] = dot;
        }
#pragma unroll
        for (int k = 0; k < 8; k++) {
            int d0 = k * 128 + lane * 4;
            atomicAdd(&s_col[d0 + 0], cs[k].x);
            atomicAdd(&s_col[d0 + 1], cs[k].y);
            atomicAdd(&s_col[d0 + 2], cs[k].z);
            atomicAdd(&s_col[d0 + 3], cs[k].w);
        }
        __syncthreads();
        float* dst = g_part + ((size_t)b * NSLICE + sl) * D_;
        for (int i = tid; i < D_ / 4; i += TPB_)
            ((float4*)dst)[i] = ((const float4*)s_col)[i];
    }
    gbar(0);

    //================ P1: top-256 radix select (blocks 0..7) ================
    if (blk < B_) {
        const int b = blk;
        unsigned* skeys = (unsigned*)smem_raw;              // 4352 u32 = 17408 B
        unsigned* hist  = (unsigned*)(smem_raw + 17408);    // 256 u32
        int* out_idx    = (int*)(smem_raw + 18432);         // 256 i32
        unsigned* wsum  = (unsigned*)(smem_raw + 19456);    // 16 u32

        for (int i = tid; i < LC_; i += TPB_)
            skeys[i] = order_key(g_sal[b * LC_ + i]);
        if (tid == 0) { s_prefix = 0u; s_krem = KEEP_; }
        __syncthreads();

        for (int pass = 0; pass < 4; pass++) {
            const int shift = 24 - 8 * pass;
            if (tid < 256) hist[tid] = 0u;
            __syncthreads();
            const unsigned pfx = s_prefix;
            const int krem = s_krem;
            for (int i = tid; i < LC_; i += TPB_) {
                unsigned k = skeys[i];
                if (pass == 0 || (k >> (shift + 8)) == pfx)
                    atomicAdd(&hist[(k >> shift) & 255u], 1u);
            }
            __syncthreads();
            if (warp == 0) {
                unsigned h[8], suf[8];
                unsigned acc = 0u;
#pragma unroll
                for (int j = 7; j >= 0; j--) { h[j] = hist[lane * 8 + j]; acc += h[j]; suf[j] = acc; }
                const unsigned tot = acc;
                unsigned inc = tot;
#pragma unroll
                for (int off = 1; off < 32; off <<= 1) {
                    unsigned v = __shfl_down_sync(0xffffffffu, inc, off);
                    if (lane + off < 32) inc += v;
                }
                const unsigned after = inc - tot;
#pragma unroll
                for (int j = 0; j < 8; j++) {
                    unsigned S  = after + suf[j];
                    unsigned Sn = after + (j < 7 ? suf[j + 1] : 0u);
                    if (S >= (unsigned)krem && Sn < (unsigned)krem) {
                        s_prefix = (pfx << 8) | (unsigned)(lane * 8 + j);
                        s_krem   = krem - (int)Sn;
                    }
                }
            }
            __syncthreads();
        }

        const unsigned thr = s_prefix;
        const unsigned rem = (unsigned)s_krem;

        const int base = tid * 9;            // 512*9 = 4608 >= 4352
        unsigned keys_l[9];
        unsigned gt = 0u, eq = 0u;
#pragma unroll
        for (int j = 0; j < 9; j++) {
            const int i = base + j;
            unsigned k = (i < LC_) ? skeys[i] : 0u;
            keys_l[j] = k;
            if (i < LC_) { gt += (k > thr); eq += (k == thr); }
        }
        const unsigned pair = (gt << 16) | eq;
        unsigned inc = pair;
#pragma unroll
        for (int off = 1; off < 32; off <<= 1) {
            unsigned v = __shfl_up_sync(0xffffffffu, inc, off);
            if (lane >= off) inc += v;
        }
        const unsigned excl = inc - pair;
        if (lane == 31) wsum[warp] = inc;
        __syncthreads();
        if (warp == 0) {
            unsigned v = (lane < 16) ? wsum[lane] : 0u;
            unsigned winc = v;
#pragma unroll
            for (int off = 1; off < 16; off <<= 1) {
                unsigned t = __shfl_up_sync(0xffffffffu, winc, off);
                if (lane >= off) winc += t;
            }
            if (lane < 16) wsum[lane] = winc - v;
        }
        __syncthreads();
        const unsigned basepair = excl + wsum[warp];
        unsigned gpref = basepair >> 16;
        unsigned epref = basepair & 0xFFFFu;
#pragma unroll
        for (int j = 0; j < 9; j++) {
            const int i = base + j;
            if (i < LC_) {
                const unsigned k = keys_l[j];
                if (k > thr) {
                    out_idx[gpref + (epref < rem ? epref : rem)] = i;
                    gpref++;
                } else if (k == thr) {
                    if (epref < rem) out_idx[gpref + epref] = i;
                    epref++;
                }
            }
        }
        __syncthreads();
        if (tid < KEEP_) g_topidx[b * KEEP_ + tid] = out_idx[tid];
    }
    gbar(1);

    //================ P2: gather kept rows + kept partial column sums ================
    {
        float* s_col = (float*)smem_raw;
        const int b  = blk / BPB_;
        const int sl = blk % BPB_;
        const int row0   = sl * GROWS;
        const int rowend = min(KEEP_, row0 + GROWS);
        for (int i = tid; i < D_; i += TPB_) s_col[i] = 0.f;
        __syncthreads();

        for (int r = row0 + warp; r < rowend; r += 16) {
            const int idx = g_topidx[b * KEEP_ + r];
            const float* src = (idx < A_)
                ? active + ((size_t)b * A_ + idx) * D_
                : x      + ((size_t)b * L_ + (idx - A_)) * D_;
            float* dst = new_active + ((size_t)b * KEEP_ + r) * D_;
            float4 v[8];
#pragma unroll
            for (int k = 0; k < 8; k++)
                v[k] = *(const float4*)(src + k * 128 + lane * 4);
#pragma unroll
            for (int k = 0; k < 8; k++) {
                *(float4*)(dst + k * 128 + lane * 4) = v[k];
                int d0 = k * 128 + lane * 4;
                atomicAdd(&s_col[d0 + 0], v[k].x);
                atomicAdd(&s_col[d0 + 1], v[k].y);
                atomicAdd(&s_col[d0 + 2], v[k].z);
                atomicAdd(&s_col[d0 + 3], v[k].w);
            }
        }
        __syncthreads();
        float* kp = g_kpart + ((size_t)b * GSLICE + sl) * D_;
        for (int i = tid; i < D_ / 4; i += TPB_)
            ((float4*)kp)[i] = ((const float4*)s_col)[i];
    }
    gbar(2);

    //================ P3: reduce partials -> cold_new + ctx (blocks 0..7) ================
    if (blk < B_) {
        const int b = blk;
        const float inv_drop = 1.0f / (float)(LC_ - KEEP_);
        const float inv_keep = 1.0f / (float)KEEP_;
        for (int d = tid; d < D_; d += TPB_) {
            float tot = 0.f, ks = 0.f;
            const float* p  = g_part  + (size_t)b * NSLICE * D_ + d;
            const float* kp = g_kpart + (size_t)b * GSLICE * D_ + d;
#pragma unroll
            for (int s = 0; s < NSLICE; s++) tot += p[(size_t)s * D_];
#pragma unroll
            for (int s = 0; s < GSLICE; s++) ks += kp[(size_t)s * D_];
            const float cn = 0.9f * cold[b * D_ + d] + 0.1f * (tot - ks) * inv_drop;
            cold_out[b * D_ + d] = cn;
            g_ctx[b * D_ + d] = ks * inv_keep + cn;
        }
    }
    gbar(3);

    //================ P4: gemv proj[b,e] (blocks 0..63, one e-row per warp) ================
    if (blk < 64) {
        float4* sctx = (float4*)smem_raw;    // 2048 float4 = 32KB
        for (int i = tid; i < B_ * 256; i += TPB_)
            sctx[i] = ((const float4*)g_ctx)[i];

        const int e = blk * 16 + warp;       // 0..1023
        const float* wr = wread + (size_t)e * D_ + lane * 4;
        float4 w[8];
#pragma unroll
        for (int k = 0; k < 8; k++)
            w[k] = *(const float4*)(wr + k * 128);
        __syncthreads();

        float acc[B_];
#pragma unroll
        for (int bb = 0; bb < B_; bb++) acc[bb] = 0.f;
#pragma unroll
        for (int k = 0; k < 8; k++) {
#pragma unroll
            for (int bb = 0; bb < B_; bb++) {
                float4 c = sctx[bb * 256 + k * 32 + lane];
                acc[bb] += w[k].x * c.x + w[k].y * c.y + w[k].z * c.z + w[k].w * c.w;
            }
        }
#pragma unroll
        for (int bb = 0; bb < B_; bb++) {
#pragma unroll
            for (int o = 16; o > 0; o >>= 1)
                acc[bb] += __shfl_down_sync(0xffffffffu, acc[bb], o);
            if (lane == 0) g_proj[bb * D_ + e] = acc[bb];
        }
    }
    gbar(4);

    //================ P5: x_out = x + proj ================
    {
        const int half = tid >> 8;           // 0..1 (two rows per 512 threads)
        const int col4 = (tid & 255) * 4;
        for (int rp0 = blk; rp0 < 16384; rp0 += GRID_ * 4) {
            float4 v[4], pp[4];
            size_t off[4];
            bool ok[4];
#pragma unroll
            for (int j = 0; j < 4; j++) {
                const int rp = rp0 + j * GRID_;
                ok[j] = (rp < 16384);
                if (ok[j]) {
                    const int gr = rp * 2 + half;          // global row 0..32767
                    off[j] = (size_t)gr * D_ + col4;
                    v[j]  = *(const float4*)(x + off[j]);
                    pp[j] = *(const float4*)(g_proj + (gr >> 12) * D_ + col4);
                }
            }
#pragma unroll
            for (int j = 0; j < 4; j++) {
                if (ok[j]) {
                    v[j].x += pp[j].x; v[j].y += pp[j].y;
                    v[j].z += pp[j].z; v[j].w += pp[j].w;
                    *(float4*)(xout + off[j]) = v[j];
                }
            }
        }
    }
}

// ---------------- launch ----------------
extern "C" void kernel_launch(void* const* d_in, const int* in_sizes, int n_in,
                              void* d_out, int out_size) {
    const float* x      = (const float*)d_in[0];   // [8,4096,1024]
    const float* active = (const float*)d_in[1];   // [8,256,1024]
    const float* cold   = (const float*)d_in[2];   // [8,1024]
    const float* w_sal  = (const float*)d_in[3];   // [1024]
    const float* w_read = (const float*)d_in[4];   // [1024,1024]

    float* xout       = (float*)d_out;
    float* new_active = xout + (size_t)in_sizes[0];
    float* cold_out   = new_active + (size_t)in_sizes[1];

    k_init<<<1, 32>>>();
    k_fused<<<GRID_, TPB_>>>(x, active, cold, w_sal, w_read,
                             xout, new_active, cold_out);
}

// round 12
// speedup vs baseline: 1.1109x; 1.0056x over previous
#include <cuda_runtime.h>
#include <cuda_bf16.h>
#include <stdint.h>

#define B_    8
#define L_    4096
#define D_    1024
#define A_    256
#define LC_   4352      // A_ + L_
#define KEEP_ 256
#define GRID_ 144       // <= SM count; one block per SM guaranteed
#define TPB_  512
#define BPB_  18        // blocks per batch (144/8)
#define NSLICE 18
#define GSLICE 18
#define SROWS 242       // ceil(4352/18)
#define GROWS 15        // ceil(256/18)

// -------- scratch (device globals; no allocation allowed) --------
__device__ unsigned g_barrier[8];
__device__ float g_sal[B_ * LC_];
__device__ float g_part[B_ * NSLICE * D_];
__device__ float g_kpart[B_ * GSLICE * D_];
__device__ int   g_topidx[B_ * KEEP_];
__device__ float g_ctx[B_ * D_];
__device__ float g_proj[B_ * D_];

__global__ void k_init() {
    if (threadIdx.x < 8) g_barrier[threadIdx.x] = 0u;
}

__device__ __forceinline__ void gbar(int ph) {
    __syncthreads();
    __threadfence();
    if (threadIdx.x == 0) {
        atomicAdd(&g_barrier[ph], 1u);
        while (atomicAdd(&g_barrier[ph], 0u) < (unsigned)GRID_) __nanosleep(32);
        __threadfence();
    }
    __syncthreads();
}

__device__ __forceinline__ unsigned int order_key(float f) {
    unsigned int u = __float_as_uint(f);
    return u ^ ((u >> 31) ? 0xFFFFFFFFu : 0x80000000u);
}

__global__ void __launch_bounds__(TPB_, 1)
k_fused(const float* __restrict__ x,
        const float* __restrict__ active,
        const float* __restrict__ cold,
        const float* __restrict__ wsal,
        const float* __restrict__ wread,
        float* __restrict__ xout,
        float* __restrict__ new_active,
        float* __restrict__ cold_out) {
    __shared__ __align__(16) char smem_raw[33024];   // max phase need: 32KB (gemv sctx)
    __shared__ unsigned s_prefix;
    __shared__ int s_krem;

    const int blk  = blockIdx.x;
    const int tid  = threadIdx.x;
    const int warp = tid >> 5;
    const int lane = tid & 31;

    //================ P0: salience + per-block partial column sums ================
    {
        float* s_col = (float*)smem_raw;
        const int b  = blk / BPB_;
        const int sl = blk % BPB_;
        for (int i = tid; i < D_; i += TPB_) s_col[i] = 0.f;

        float4 ws[8];
#pragma unroll
        for (int k = 0; k < 8; k++)
            ws[k] = *(const float4*)(wsal + k * 128 + lane * 4);
        float4 cs[8];
#pragma unroll
        for (int k = 0; k < 8; k++) cs[k] = make_float4(0.f, 0.f, 0.f, 0.f);
        __syncthreads();

        const int row0   = sl * SROWS;
        const int rowend = min(LC_, row0 + SROWS);
        for (int t = row0 + warp; t < rowend; t += 16) {
            const float* src = (t < A_)
                ? active + ((size_t)b * A_ + t) * D_
                : x      + ((size_t)b * L_ + (t - A_)) * D_;
            float dot = 0.f;
#pragma unroll
            for (int k = 0; k < 8; k++) {
                float4 v = *(const float4*)(src + k * 128 + lane * 4);
                dot += v.x * ws[k].x + v.y * ws[k].y + v.z * ws[k].z + v.w * ws[k].w;
                cs[k].x += v.x; cs[k].y += v.y; cs[k].z += v.z; cs[k].w += v.w;
            }
#pragma unroll
            for (int o = 16; o > 0; o >>= 1)
                dot += __shfl_down_sync(0xffffffffu, dot, o);
            if (lane == 0) g_sal[b * LC_ + t] = dot;
        }
#pragma unroll
        for (int k = 0; k < 8; k++) {
            int d0 = k * 128 + lane * 4;
            atomicAdd(&s_col[d0 + 0], cs[k].x);
            atomicAdd(&s_col[d0 + 1], cs[k].y);
            atomicAdd(&s_col[d0 + 2], cs[k].z);
            atomicAdd(&s_col[d0 + 3], cs[k].w);
        }
        __syncthreads();
        float* dst = g_part + ((size_t)b * NSLICE + sl) * D_;
        for (int i = tid; i < D_ / 4; i += TPB_)
            ((float4*)dst)[i] = ((const float4*)s_col)[i];
    }
    gbar(0);

    //================ P1: top-256 radix select (blocks 0..7) ================
    if (blk < B_) {
        const int b = blk;
        unsigned* skeys = (unsigned*)smem_raw;              // 4352 u32 = 17408 B
        unsigned* hist  = (unsigned*)(smem_raw + 17408);    // 256 u32
        int* out_idx    = (int*)(smem_raw + 18432);         // 256 i32
        unsigned* wsum  = (unsigned*)(smem_raw + 19456);    // 16 u32

        for (int i = tid; i < LC_; i += TPB_)
            skeys[i] = order_key(g_sal[b * LC_ + i]);
        if (tid == 0) { s_prefix = 0u; s_krem = KEEP_; }
        __syncthreads();

        for (int pass = 0; pass < 4; pass++) {
            const int shift = 24 - 8 * pass;
            if (tid < 256) hist[tid] = 0u;
            __syncthreads();
            const unsigned pfx = s_prefix;
            const int krem = s_krem;
            for (int i = tid; i < LC_; i += TPB_) {
                unsigned k = skeys[i];
                if (pass == 0 || (k >> (shift + 8)) == pfx)
                    atomicAdd(&hist[(k >> shift) & 255u], 1u);
            }
            __syncthreads();
            if (warp == 0) {
                unsigned h[8], suf[8];
                unsigned acc = 0u;
#pragma unroll
                for (int j = 7; j >= 0; j--) { h[j] = hist[lane * 8 + j]; acc += h[j]; suf[j] = acc; }
                const unsigned tot = acc;
                unsigned inc = tot;
#pragma unroll
                for (int off = 1; off < 32; off <<= 1) {
                    unsigned v = __shfl_down_sync(0xffffffffu, inc, off);
                    if (lane + off < 32) inc += v;
                }
                const unsigned after = inc - tot;
#pragma unroll
                for (int j = 0; j < 8; j++) {
                    unsigned S  = after + suf[j];
                    unsigned Sn = after + (j < 7 ? suf[j + 1] : 0u);
                    if (S >= (unsigned)krem && Sn < (unsigned)krem) {
                        s_prefix = (pfx << 8) | (unsigned)(lane * 8 + j);
                        s_krem   = krem - (int)Sn;
                    }
                }
            }
            __syncthreads();
        }

        const unsigned thr = s_prefix;
        const unsigned rem = (unsigned)s_krem;

        const int base = tid * 9;            // 512*9 = 4608 >= 4352
        unsigned keys_l[9];
        unsigned gt = 0u, eq = 0u;
#pragma unroll
        for (int j = 0; j < 9; j++) {
            const int i = base + j;
            unsigned k = (i < LC_) ? skeys[i] : 0u;
            keys_l[j] = k;
            if (i < LC_) { gt += (k > thr); eq += (k == thr); }
        }
        const unsigned pair = (gt << 16) | eq;
        unsigned inc = pair;
#pragma unroll
        for (int off = 1; off < 32; off <<= 1) {
            unsigned v = __shfl_up_sync(0xffffffffu, inc, off);
            if (lane >= off) inc += v;
        }
        const unsigned excl = inc - pair;
        if (lane == 31) wsum[warp] = inc;
        __syncthreads();
        if (warp == 0) {
            unsigned v = (lane < 16) ? wsum[lane] : 0u;
            unsigned winc = v;
#pragma unroll
            for (int off = 1; off < 16; off <<= 1) {
                unsigned t = __shfl_up_sync(0xffffffffu, winc, off);
                if (lane >= off) winc += t;
            }
            if (lane < 16) wsum[lane] = winc - v;
        }
        __syncthreads();
        const unsigned basepair = excl + wsum[warp];
        unsigned gpref = basepair >> 16;
        unsigned epref = basepair & 0xFFFFu;
#pragma unroll
        for (int j = 0; j < 9; j++) {
            const int i = base + j;
            if (i < LC_) {
                const unsigned k = keys_l[j];
                if (k > thr) {
                    out_idx[gpref + (epref < rem ? epref : rem)] = i;
                    gpref++;
                } else if (k == thr) {
                    if (epref < rem) out_idx[gpref + epref] = i;
                    epref++;
                }
            }
        }
        __syncthreads();
        if (tid < KEEP_) g_topidx[b * KEEP_ + tid] = out_idx[tid];
    }
    gbar(1);

    //================ P2: gather kept rows + kept partial column sums ================
    {
        float* s_col = (float*)smem_raw;
        const int b  = blk / BPB_;
        const int sl = blk % BPB_;
        const int row0   = sl * GROWS;
        const int rowend = min(KEEP_, row0 + GROWS);
        for (int i = tid; i < D_; i += TPB_) s_col[i] = 0.f;
        __syncthreads();

        for (int r = row0 + warp; r < rowend; r += 16) {
            const int idx = g_topidx[b * KEEP_ + r];
            const float* src = (idx < A_)
                ? active + ((size_t)b * A_ + idx) * D_
                : x      + ((size_t)b * L_ + (idx - A_)) * D_;
            float* dst = new_active + ((size_t)b * KEEP_ + r) * D_;
            float4 v[8];
#pragma unroll
            for (int k = 0; k < 8; k++)
                v[k] = *(const float4*)(src + k * 128 + lane * 4);
#pragma unroll
            for (int k = 0; k < 8; k++) {
                *(float4*)(dst + k * 128 + lane * 4) = v[k];
                int d0 = k * 128 + lane * 4;
                atomicAdd(&s_col[d0 + 0], v[k].x);
                atomicAdd(&s_col[d0 + 1], v[k].y);
                atomicAdd(&s_col[d0 + 2], v[k].z);
                atomicAdd(&s_col[d0 + 3], v[k].w);
            }
        }
        __syncthreads();
        float* kp = g_kpart + ((size_t)b * GSLICE + sl) * D_;
        for (int i = tid; i < D_ / 4; i += TPB_)
            ((float4*)kp)[i] = ((const float4*)s_col)[i];
    }
    gbar(2);

    //================ P3: reduce partials -> cold_new + ctx (blocks 0..7) ================
    if (blk < B_) {
        const int b = blk;
        const float inv_drop = 1.0f / (float)(LC_ - KEEP_);
        const float inv_keep = 1.0f / (float)KEEP_;
        for (int d = tid; d < D_; d += TPB_) {
            float tot = 0.f, ks = 0.f;
            const float* p  = g_part  + (size_t)b * NSLICE * D_ + d;
            const float* kp = g_kpart + (size_t)b * GSLICE * D_ + d;
#pragma unroll
            for (int s = 0; s < NSLICE; s++) tot += p[(size_t)s * D_];
#pragma unroll
            for (int s = 0; s < GSLICE; s++) ks += kp[(size_t)s * D_];
            const float cn = 0.9f * cold[b * D_ + d] + 0.1f * (tot - ks) * inv_drop;
            cold_out[b * D_ + d] = cn;
            g_ctx[b * D_ + d] = ks * inv_keep + cn;
        }
    }
    gbar(3);

    //================ P4: gemv proj[b,e] (blocks 0..63, one e-row per warp) ================
    if (blk < 64) {
        float4* sctx = (float4*)smem_raw;    // 2048 float4 = 32KB
        for (int i = tid; i < B_ * 256; i += TPB_)
            sctx[i] = ((const float4*)g_ctx)[i];

        const int e = blk * 16 + warp;       // 0..1023
        const float* wr = wread + (size_t)e * D_ + lane * 4;
        float4 w[8];
#pragma unroll
        for (int k = 0; k < 8; k++)
            w[k] = *(const float4*)(wr + k * 128);
        __syncthreads();

        float acc[B_];
#pragma unroll
        for (int bb = 0; bb < B_; bb++) acc[bb] = 0.f;
#pragma unroll
        for (int k = 0; k < 8; k++) {
#pragma unroll
            for (int bb = 0; bb < B_; bb++) {
                float4 c = sctx[bb * 256 + k * 32 + lane];
                acc[bb] += w[k].x * c.x + w[k].y * c.y + w[k].z * c.z + w[k].w * c.w;
            }
        }
#pragma unroll
        for (int bb = 0; bb < B_; bb++) {
#pragma unroll
            for (int o = 16; o > 0; o >>= 1)
                acc[bb] += __shfl_down_sync(0xffffffffu, acc[bb], o);
            if (lane == 0) g_proj[bb * D_ + e] = acc[bb];
        }
    }
    gbar(4);

    //================ P5: x_out = x + proj ================
    // grid-stride over 2048 groups of 16 rows; a group never crosses a batch
    // boundary (4096 % 16 == 0) -> proj loaded once per group. 8 row-pairs
    // front-batched per thread: 128B in flight/thread = 64KB/SM.
    {
        const int half = tid >> 8;           // 0..1
        const int col4 = (tid & 255) * 4;
        for (int g = blk; g < 2048; g += GRID_) {
            const int r0 = g * 16;           // global row 0..32767, 16-aligned
            const float4 pp = *(const float4*)(g_proj + (r0 >> 12) * D_ + col4);
            const float* xs = x    + (size_t)(r0 + half) * D_ + col4;
            float*       os = xout + (size_t)(r0 + half) * D_ + col4;
            float4 v[8];
#pragma unroll
            for (int j = 0; j < 8; j++)
                v[j] = *(const float4*)(xs + (size_t)(j * 2) * D_);
#pragma unroll
            for (int j = 0; j < 8; j++) {
                v[j].x += pp.x; v[j].y += pp.y; v[j].z += pp.z; v[j].w += pp.w;
                *(float4*)(os + (size_t)(j * 2) * D_) = v[j];
            }
        }
    }
}

// ---------------- launch ----------------
extern "C" void kernel_launch(void* const* d_in, const int* in_sizes, int n_in,
                              void* d_out, int out_size) {
    const float* x      = (const float*)d_in[0];   // [8,4096,1024]
    const float* active = (const float*)d_in[1];   // [8,256,1024]
    const float* cold   = (const float*)d_in[2];   // [8,1024]
    const float* w_sal  = (const float*)d_in[3];   // [1024]
    const float* w_read = (const float*)d_in[4];   // [1024,1024]

    float* xout       = (float*)d_out;
    float* new_active = xout + (size_t)in_sizes[0];
    float* cold_out   = new_active + (size_t)in_sizes[1];

    k_init<<<1, 32>>>();
    k_fused<<<GRID_, TPB_>>>(x, active, cold, w_sal, w_read,
                             xout, new_active, cold_out);
}

// round 13
// speedup vs baseline: 1.1275x; 1.0149x over previous
#include <cuda_runtime.h>
#include <cuda_bf16.h>
#include <stdint.h>

#define B_    8
#define L_    4096
#define D_    1024
#define A_    256
#define LC_   4352      // A_ + L_
#define KEEP_ 256
#define GRID_ 144       // <= SM count; one block per SM guaranteed
#define TPB_  512
#define BPB_  18        // blocks per batch (144/8)
#define NSLICE 18
#define GSLICE 18
#define SROWS 242       // ceil(4352/18)
#define GROWS 15        // ceil(256/18)

#define CDROP_ (0.1f / 4096.0f)                    // 0.1 / n_dropped
#define ALPHA_ (1.0f / 256.0f - 0.1f / 4096.0f)    // kept coefficient in ctx

// -------- scratch (device globals; no allocation allowed) --------
__device__ unsigned g_barrier[8];
__device__ unsigned g_uflag;      // release: u vector ready
__device__ unsigned g_kflag;      // release: kept ctx ready
__device__ float g_sal[B_ * LC_];
__device__ float g_part[B_ * NSLICE * D_];
__device__ float g_kpart[B_ * GSLICE * D_];
__device__ int   g_topidx[B_ * KEEP_];
__device__ float g_u[B_ * D_];       // 0.9*cold + CDROP*totsum
__device__ float g_kctx[B_ * D_];    // ALPHA*keptsum
__device__ float g_proj1[B_ * D_];   // u @ W^T
__device__ float g_proj[B_ * D_];    // full proj

__global__ void k_init() {
    if (threadIdx.x < 8) g_barrier[threadIdx.x] = 0u;
    if (threadIdx.x == 8) g_uflag = 0u;
    if (threadIdx.x == 9) g_kflag = 0u;
}

__device__ __forceinline__ void gbar(int ph) {
    __syncthreads();
    __threadfence();
    if (threadIdx.x == 0) {
        atomicAdd(&g_barrier[ph], 1u);
        while (atomicAdd(&g_barrier[ph], 0u) < (unsigned)GRID_) __nanosleep(32);
        __threadfence();
    }
    __syncthreads();
}

__device__ __forceinline__ unsigned int order_key(float f) {
    unsigned int u = __float_as_uint(f);
    return u ^ ((u >> 31) ? 0xFFFFFFFFu : 0x80000000u);
}

__global__ void __launch_bounds__(TPB_, 1)
k_fused(const float* __restrict__ x,
        const float* __restrict__ active,
        const float* __restrict__ cold,
        const float* __restrict__ wsal,
        const float* __restrict__ wread,
        float* __restrict__ xout,
        float* __restrict__ new_active,
        float* __restrict__ cold_out) {
    __shared__ __align__(16) char smem_raw[33024];   // max phase need: 32KB
    __shared__ unsigned s_prefix;
    __shared__ int s_krem;

    const int blk  = blockIdx.x;
    const int tid  = threadIdx.x;
    const int warp = tid >> 5;
    const int lane = tid & 31;

    //================ P0: salience + per-block partial column sums ================
    {
        float* s_col = (float*)smem_raw;
        const int b  = blk / BPB_;
        const int sl = blk % BPB_;
        for (int i = tid; i < D_; i += TPB_) s_col[i] = 0.f;

        float4 ws[8];
#pragma unroll
        for (int k = 0; k < 8; k++)
            ws[k] = *(const float4*)(wsal + k * 128 + lane * 4);
        float4 cs[8];
#pragma unroll
        for (int k = 0; k < 8; k++) cs[k] = make_float4(0.f, 0.f, 0.f, 0.f);
        __syncthreads();

        const int row0   = sl * SROWS;
        const int rowend = min(LC_, row0 + SROWS);
        for (int t = row0 + warp; t < rowend; t += 16) {
            const float* src = (t < A_)
                ? active + ((size_t)b * A_ + t) * D_
                : x      + ((size_t)b * L_ + (t - A_)) * D_;
            float dot = 0.f;
#pragma unroll
            for (int k = 0; k < 8; k++) {
                float4 v = *(const float4*)(src + k * 128 + lane * 4);
                dot += v.x * ws[k].x + v.y * ws[k].y + v.z * ws[k].z + v.w * ws[k].w;
                cs[k].x += v.x; cs[k].y += v.y; cs[k].z += v.z; cs[k].w += v.w;
            }
#pragma unroll
            for (int o = 16; o > 0; o >>= 1)
                dot += __shfl_down_sync(0xffffffffu, dot, o);
            if (lane == 0) g_sal[b * LC_ + t] = dot;
        }
#pragma unroll
        for (int k = 0; k < 8; k++) {
            int d0 = k * 128 + lane * 4;
            atomicAdd(&s_col[d0 + 0], cs[k].x);
            atomicAdd(&s_col[d0 + 1], cs[k].y);
            atomicAdd(&s_col[d0 + 2], cs[k].z);
            atomicAdd(&s_col[d0 + 3], cs[k].w);
        }
        __syncthreads();
        float* dst = g_part + ((size_t)b * NSLICE + sl) * D_;
        for (int i = tid; i < D_ / 4; i += TPB_)
            ((float4*)dst)[i] = ((const float4*)s_col)[i];
    }
    gbar(0);

    //================ P1: u-reduce (0..7) || topk (8..15) || gemv1 u@W^T (16..79) ================
    if (blk < 8) {
        // ---- u-reduce: totsum -> u = 0.9*cold + CDROP*tot ----
        const int b = blk;
        for (int d = tid; d < D_; d += TPB_) {
            float tot = 0.f;
            const float* p = g_part + (size_t)b * NSLICE * D_ + d;
#pragma unroll
            for (int s = 0; s < NSLICE; s++) tot += p[(size_t)s * D_];
            g_u[b * D_ + d] = 0.9f * cold[b * D_ + d] + CDROP_ * tot;
        }
        __threadfence();
        __syncthreads();
        if (tid == 0) atomicAdd(&g_uflag, 1u);   // release
    } else if (blk < 16) {
        // ---- topk for batch blk-8 ----
        const int b = blk - 8;
        unsigned* skeys = (unsigned*)smem_raw;              // 4352 u32 = 17408 B
        unsigned* hist  = (unsigned*)(smem_raw + 17408);    // 256 u32
        int* out_idx    = (int*)(smem_raw + 18432);         // 256 i32
        unsigned* wsum  = (unsigned*)(smem_raw + 19456);    // 16 u32

        for (int i = tid; i < LC_; i += TPB_)
            skeys[i] = order_key(g_sal[b * LC_ + i]);
        if (tid == 0) { s_prefix = 0u; s_krem = KEEP_; }
        __syncthreads();

        for (int pass = 0; pass < 4; pass++) {
            const int shift = 24 - 8 * pass;
            if (tid < 256) hist[tid] = 0u;
            __syncthreads();
            const unsigned pfx = s_prefix;
            const int krem = s_krem;
            for (int i = tid; i < LC_; i += TPB_) {
                unsigned k = skeys[i];
                if (pass == 0 || (k >> (shift + 8)) == pfx)
                    atomicAdd(&hist[(k >> shift) & 255u], 1u);
            }
            __syncthreads();
            if (warp == 0) {
                unsigned h[8], suf[8];
                unsigned acc = 0u;
#pragma unroll
                for (int j = 7; j >= 0; j--) { h[j] = hist[lane * 8 + j]; acc += h[j]; suf[j] = acc; }
                const unsigned tot = acc;
                unsigned inc = tot;
#pragma unroll
                for (int off = 1; off < 32; off <<= 1) {
                    unsigned v = __shfl_down_sync(0xffffffffu, inc, off);
                    if (lane + off < 32) inc += v;
                }
                const unsigned after = inc - tot;
#pragma unroll
                for (int j = 0; j < 8; j++) {
                    unsigned S  = after + suf[j];
                    unsigned Sn = after + (j < 7 ? suf[j + 1] : 0u);
                    if (S >= (unsigned)krem && Sn < (unsigned)krem) {
                        s_prefix = (pfx << 8) | (unsigned)(lane * 8 + j);
                        s_krem   = krem - (int)Sn;
                    }
                }
            }
            __syncthreads();
        }

        const unsigned thr = s_prefix;
        const unsigned rem = (unsigned)s_krem;

        const int base = tid * 9;            // 512*9 = 4608 >= 4352
        unsigned keys_l[9];
        unsigned gt = 0u, eq = 0u;
#pragma unroll
        for (int j = 0; j < 9; j++) {
            const int i = base + j;
            unsigned k = (i < LC_) ? skeys[i] : 0u;
            keys_l[j] = k;
            if (i < LC_) { gt += (k > thr); eq += (k == thr); }
        }
        const unsigned pair = (gt << 16) | eq;
        unsigned inc = pair;
#pragma unroll
        for (int off = 1; off < 32; off <<= 1) {
            unsigned v = __shfl_up_sync(0xffffffffu, inc, off);
            if (lane >= off) inc += v;
        }
        const unsigned excl = inc - pair;
        if (lane == 31) wsum[warp] = inc;
        __syncthreads();
        if (warp == 0) {
            unsigned v = (lane < 16) ? wsum[lane] : 0u;
            unsigned winc = v;
#pragma unroll
            for (int off = 1; off < 16; off <<= 1) {
                unsigned t = __shfl_up_sync(0xffffffffu, winc, off);
                if (lane >= off) winc += t;
            }
            if (lane < 16) wsum[lane] = winc - v;
        }
        __syncthreads();
        const unsigned basepair = excl + wsum[warp];
        unsigned gpref = basepair >> 16;
        unsigned epref = basepair & 0xFFFFu;
#pragma unroll
        for (int j = 0; j < 9; j++) {
            const int i = base + j;
            if (i < LC_) {
                const unsigned k = keys_l[j];
                if (k > thr) {
                    out_idx[gpref + (epref < rem ? epref : rem)] = i;
                    gpref++;
                } else if (k == thr) {
                    if (epref < rem) out_idx[gpref + epref] = i;
                    epref++;
                }
            }
        }
        __syncthreads();
        if (tid < KEEP_) g_topidx[b * KEEP_ + tid] = out_idx[tid];
    } else if (blk < 80) {
        // ---- gemv1: proj1[b,e] = sum_d u[b,d]*wread[e,d]; W DRAM read hidden here ----
        float4* sctx = (float4*)smem_raw;    // 32KB
        const int e = (blk - 16) * 16 + warp;            // 0..1023
        const float* wr = wread + (size_t)e * D_ + lane * 4;
        float4 w[8];
#pragma unroll
        for (int k = 0; k < 8; k++)
            w[k] = *(const float4*)(wr + k * 128);       // front-batched, u-independent

        if (tid == 0) {
            while (atomicAdd(&g_uflag, 0u) < 8u) __nanosleep(32);
        }
        __syncthreads();
        __threadfence();
        for (int i = tid; i < B_ * 256; i += TPB_)
            sctx[i] = ((const float4*)g_u)[i];
        __syncthreads();

        float acc[B_];
#pragma unroll
        for (int bb = 0; bb < B_; bb++) acc[bb] = 0.f;
#pragma unroll
        for (int k = 0; k < 8; k++) {
#pragma unroll
            for (int bb = 0; bb < B_; bb++) {
                float4 c = sctx[bb * 256 + k * 32 + lane];
                acc[bb] += w[k].x * c.x + w[k].y * c.y + w[k].z * c.z + w[k].w * c.w;
            }
        }
#pragma unroll
        for (int bb = 0; bb < B_; bb++) {
#pragma unroll
            for (int o = 16; o > 0; o >>= 1)
                acc[bb] += __shfl_down_sync(0xffffffffu, acc[bb], o);
            if (lane == 0) g_proj1[bb * D_ + e] = acc[bb];
        }
    }
    gbar(1);

    //================ P2: gather kept rows + kept partial column sums ================
    {
        float* s_col = (float*)smem_raw;
        const int b  = blk / BPB_;
        const int sl = blk % BPB_;
        const int row0   = sl * GROWS;
        const int rowend = min(KEEP_, row0 + GROWS);
        for (int i = tid; i < D_; i += TPB_) s_col[i] = 0.f;
        __syncthreads();

        for (int r = row0 + warp; r < rowend; r += 16) {
            const int idx = g_topidx[b * KEEP_ + r];
            const float* src = (idx < A_)
                ? active + ((size_t)b * A_ + idx) * D_
                : x      + ((size_t)b * L_ + (idx - A_)) * D_;
            float* dst = new_active + ((size_t)b * KEEP_ + r) * D_;
            float4 v[8];
#pragma unroll
            for (int k = 0; k < 8; k++)
                v[k] = *(const float4*)(src + k * 128 + lane * 4);
#pragma unroll
            for (int k = 0; k < 8; k++) {
                *(float4*)(dst + k * 128 + lane * 4) = v[k];
                int d0 = k * 128 + lane * 4;
                atomicAdd(&s_col[d0 + 0], v[k].x);
                atomicAdd(&s_col[d0 + 1], v[k].y);
                atomicAdd(&s_col[d0 + 2], v[k].z);
                atomicAdd(&s_col[d0 + 3], v[k].w);
            }
        }
        __syncthreads();
        float* kp = g_kpart + ((size_t)b * GSLICE + sl) * D_;
        for (int i = tid; i < D_ / 4; i += TPB_)
            ((float4*)kp)[i] = ((const float4*)s_col)[i];
    }
    gbar(2);

    //================ P3: kept-reduce (0..7) || gemv2 (8..71), W is L2-hot ================
    if (blk < 8) {
        const int b = blk;
        for (int d = tid; d < D_; d += TPB_) {
            float ks = 0.f;
            const float* kp = g_kpart + (size_t)b * GSLICE * D_ + d;
#pragma unroll
            for (int s = 0; s < GSLICE; s++) ks += kp[(size_t)s * D_];
            cold_out[b * D_ + d] = g_u[b * D_ + d] - CDROP_ * ks;
            g_kctx[b * D_ + d]   = ALPHA_ * ks;
        }
        __threadfence();
        __syncthreads();
        if (tid == 0) atomicAdd(&g_kflag, 1u);   // release
    } else if (blk < 72) {
        float4* sctx = (float4*)smem_raw;    // 32KB
        const int e = (blk - 8) * 16 + warp;             // 0..1023
        const float* wr = wread + (size_t)e * D_ + lane * 4;
        float4 w[8];
#pragma unroll
        for (int k = 0; k < 8; k++)
            w[k] = *(const float4*)(wr + k * 128);       // L2-hot

        if (tid == 0) {
            while (atomicAdd(&g_kflag, 0u) < 8u) __nanosleep(32);
        }
        __syncthreads();
        __threadfence();
        for (int i = tid; i < B_ * 256; i += TPB_)
            sctx[i] = ((const float4*)g_kctx)[i];
        __syncthreads();

        float acc[B_];
#pragma unroll
        for (int bb = 0; bb < B_; bb++) acc[bb] = 0.f;
#pragma unroll
        for (int k = 0; k < 8; k++) {
#pragma unroll
            for (int bb = 0; bb < B_; bb++) {
                float4 c = sctx[bb * 256 + k * 32 + lane];
                acc[bb] += w[k].x * c.x + w[k].y * c.y + w[k].z * c.z + w[k].w * c.w;
            }
        }
#pragma unroll
        for (int bb = 0; bb < B_; bb++) {
#pragma unroll
            for (int o = 16; o > 0; o >>= 1)
                acc[bb] += __shfl_down_sync(0xffffffffu, acc[bb], o);
            if (lane == 0) g_proj[bb * D_ + e] = g_proj1[bb * D_ + e] + acc[bb];
        }
    }
    gbar(3);

    //================ P4: x_out = x + proj ================
    {
        const int half = tid >> 8;           // 0..1
        const int col4 = (tid & 255) * 4;
        for (int g = blk; g < 2048; g += GRID_) {
            const int r0 = g * 16;           // 16-aligned global row; never crosses batch
            const float4 pp = *(const float4*)(g_proj + (r0 >> 12) * D_ + col4);
            const float* xs = x    + (size_t)(r0 + half) * D_ + col4;
            float*       os = xout + (size_t)(r0 + half) * D_ + col4;
            float4 v[8];
#pragma unroll
            for (int j = 0; j < 8; j++)
                v[j] = *(const float4*)(xs + (size_t)(j * 2) * D_);
#pragma unroll
            for (int j = 0; j < 8; j++) {
                v[j].x += pp.x; v[j].y += pp.y; v[j].z += pp.z; v[j].w += pp.w;
                *(float4*)(os + (size_t)(j * 2) * D_) = v[j];
            }
        }
    }
}

// ---------------- launch ----------------
extern "C" void kernel_launch(void* const* d_in, const int* in_sizes, int n_in,
                              void* d_out, int out_size) {
    const float* x      = (const float*)d_in[0];   // [8,4096,1024]
    const float* active = (const float*)d_in[1];   // [8,256,1024]
    const float* cold   = (const float*)d_in[2];   // [8,1024]
    const float* w_sal  = (const float*)d_in[3];   // [1024]
    const float* w_read = (const float*)d_in[4];   // [1024,1024]

    float* xout       = (float*)d_out;
    float* new_active = xout + (size_t)in_sizes[0];
    float* cold_out   = new_active + (size_t)in_sizes[1];

    k_init<<<1, 32>>>();
    k_fused<<<GRID_, TPB_>>>(x, active, cold, w_sal, w_read,
                             xout, new_active, cold_out);
}

// round 14
// speedup vs baseline: 1.1279x; 1.0003x over previous
#include <cuda_runtime.h>
#include <cuda_bf16.h>
#include <stdint.h>

#define B_    8
#define L_    4096
#define D_    1024
#define A_    256
#define LC_   4352      // A_ + L_
#define KEEP_ 256
#define GRID_ 144       // <= SM count; one block per SM guaranteed
#define TPB_  512
#define BPB_  18        // blocks per batch (144/8)
#define NSLICE 18
#define GSLICE 18
#define SROWS 242       // ceil(4352/18)
#define GROWS 15        // ceil(256/18)

#define CDROP_ (0.1f / 4096.0f)                    // 0.1 / n_dropped
#define ALPHA_ (1.0f / 256.0f - 0.1f / 4096.0f)    // kept coefficient in ctx

// -------- scratch (device globals; no allocation allowed) --------
__device__ unsigned g_barrier[8];
__device__ unsigned g_uflag;      // release: u vector ready
__device__ unsigned g_kflag;      // release: kept ctx ready
__device__ float g_sal[B_ * LC_];
__device__ float g_part[B_ * NSLICE * D_];
__device__ float g_kpart[B_ * GSLICE * D_];
__device__ int   g_topidx[B_ * KEEP_];
__device__ float g_u[B_ * D_];       // 0.9*cold + CDROP*totsum
__device__ float g_kctx[B_ * D_];    // ALPHA*keptsum
__device__ float g_proj1[B_ * D_];   // u @ W^T
__device__ float g_proj[B_ * D_];    // full proj

__global__ void k_init() {
    if (threadIdx.x < 8) g_barrier[threadIdx.x] = 0u;
    if (threadIdx.x == 8) g_uflag = 0u;
    if (threadIdx.x == 9) g_kflag = 0u;
}

__device__ __forceinline__ void gbar(int ph) {
    __syncthreads();
    __threadfence();
    if (threadIdx.x == 0) {
        atomicAdd(&g_barrier[ph], 1u);
        while (atomicAdd(&g_barrier[ph], 0u) < (unsigned)GRID_) __nanosleep(32);
        __threadfence();
    }
    __syncthreads();
}

__device__ __forceinline__ unsigned int order_key(float f) {
    unsigned int u = __float_as_uint(f);
    return u ^ ((u >> 31) ? 0xFFFFFFFFu : 0x80000000u);
}

// ================= K1: persistent — salience .. gemv (phases P0..P3) =================
__global__ void __launch_bounds__(TPB_, 1)
k_fused(const float* __restrict__ x,
        const float* __restrict__ active,
        const float* __restrict__ cold,
        const float* __restrict__ wsal,
        const float* __restrict__ wread,
        float* __restrict__ new_active,
        float* __restrict__ cold_out) {
    __shared__ __align__(16) char smem_raw[33024];
    __shared__ unsigned s_prefix;
    __shared__ int s_krem;

    const int blk  = blockIdx.x;
    const int tid  = threadIdx.x;
    const int warp = tid >> 5;
    const int lane = tid & 31;

    //================ P0: salience + per-block partial column sums ================
    {
        float* s_col = (float*)smem_raw;
        const int b  = blk / BPB_;
        const int sl = blk % BPB_;
        for (int i = tid; i < D_; i += TPB_) s_col[i] = 0.f;

        float4 ws[8];
#pragma unroll
        for (int k = 0; k < 8; k++)
            ws[k] = *(const float4*)(wsal + k * 128 + lane * 4);
        float4 cs[8];
#pragma unroll
        for (int k = 0; k < 8; k++) cs[k] = make_float4(0.f, 0.f, 0.f, 0.f);
        __syncthreads();

        const int row0   = sl * SROWS;
        const int rowend = min(LC_, row0 + SROWS);
        for (int t = row0 + warp; t < rowend; t += 16) {
            const float* src = (t < A_)
                ? active + ((size_t)b * A_ + t) * D_
                : x      + ((size_t)b * L_ + (t - A_)) * D_;
            float dot = 0.f;
#pragma unroll
            for (int k = 0; k < 8; k++) {
                float4 v = *(const float4*)(src + k * 128 + lane * 4);
                dot += v.x * ws[k].x + v.y * ws[k].y + v.z * ws[k].z + v.w * ws[k].w;
                cs[k].x += v.x; cs[k].y += v.y; cs[k].z += v.z; cs[k].w += v.w;
            }
#pragma unroll
            for (int o = 16; o > 0; o >>= 1)
                dot += __shfl_down_sync(0xffffffffu, dot, o);
            if (lane == 0) g_sal[b * LC_ + t] = dot;
        }
#pragma unroll
        for (int k = 0; k < 8; k++) {
            int d0 = k * 128 + lane * 4;
            atomicAdd(&s_col[d0 + 0], cs[k].x);
            atomicAdd(&s_col[d0 + 1], cs[k].y);
            atomicAdd(&s_col[d0 + 2], cs[k].z);
            atomicAdd(&s_col[d0 + 3], cs[k].w);
        }
        __syncthreads();
        float* dst = g_part + ((size_t)b * NSLICE + sl) * D_;
        for (int i = tid; i < D_ / 4; i += TPB_)
            ((float4*)dst)[i] = ((const float4*)s_col)[i];
    }
    gbar(0);

    //================ P1: u-reduce (0..7) || topk (8..15) || gemv1 u@W^T (16..79) ================
    if (blk < 8) {
        const int b = blk;
        for (int d = tid; d < D_; d += TPB_) {
            float tot = 0.f;
            const float* p = g_part + (size_t)b * NSLICE * D_ + d;
#pragma unroll
            for (int s = 0; s < NSLICE; s++) tot += p[(size_t)s * D_];
            g_u[b * D_ + d] = 0.9f * cold[b * D_ + d] + CDROP_ * tot;
        }
        __threadfence();
        __syncthreads();
        if (tid == 0) atomicAdd(&g_uflag, 1u);   // release
    } else if (blk < 16) {
        const int b = blk - 8;
        unsigned* skeys = (unsigned*)smem_raw;              // 4352 u32
        unsigned* hist  = (unsigned*)(smem_raw + 17408);
        int* out_idx    = (int*)(smem_raw + 18432);
        unsigned* wsum  = (unsigned*)(smem_raw + 19456);

        for (int i = tid; i < LC_; i += TPB_)
            skeys[i] = order_key(g_sal[b * LC_ + i]);
        if (tid == 0) { s_prefix = 0u; s_krem = KEEP_; }
        __syncthreads();

        for (int pass = 0; pass < 4; pass++) {
            const int shift = 24 - 8 * pass;
            if (tid < 256) hist[tid] = 0u;
            __syncthreads();
            const unsigned pfx = s_prefix;
            const int krem = s_krem;
            for (int i = tid; i < LC_; i += TPB_) {
                unsigned k = skeys[i];
                if (pass == 0 || (k >> (shift + 8)) == pfx)
                    atomicAdd(&hist[(k >> shift) & 255u], 1u);
            }
            __syncthreads();
            if (warp == 0) {
                unsigned h[8], suf[8];
                unsigned acc = 0u;
#pragma unroll
                for (int j = 7; j >= 0; j--) { h[j] = hist[lane * 8 + j]; acc += h[j]; suf[j] = acc; }
                const unsigned tot = acc;
                unsigned inc = tot;
#pragma unroll
                for (int off = 1; off < 32; off <<= 1) {
                    unsigned v = __shfl_down_sync(0xffffffffu, inc, off);
                    if (lane + off < 32) inc += v;
                }
                const unsigned after = inc - tot;
#pragma unroll
                for (int j = 0; j < 8; j++) {
                    unsigned S  = after + suf[j];
                    unsigned Sn = after + (j < 7 ? suf[j + 1] : 0u);
                    if (S >= (unsigned)krem && Sn < (unsigned)krem) {
                        s_prefix = (pfx << 8) | (unsigned)(lane * 8 + j);
                        s_krem   = krem - (int)Sn;
                    }
                }
            }
            __syncthreads();
        }

        const unsigned thr = s_prefix;
        const unsigned rem = (unsigned)s_krem;

        const int base = tid * 9;
        unsigned keys_l[9];
        unsigned gt = 0u, eq = 0u;
#pragma unroll
        for (int j = 0; j < 9; j++) {
            const int i = base + j;
            unsigned k = (i < LC_) ? skeys[i] : 0u;
            keys_l[j] = k;
            if (i < LC_) { gt += (k > thr); eq += (k == thr); }
        }
        const unsigned pair = (gt << 16) | eq;
        unsigned inc = pair;
#pragma unroll
        for (int off = 1; off < 32; off <<= 1) {
            unsigned v = __shfl_up_sync(0xffffffffu, inc, off);
            if (lane >= off) inc += v;
        }
        const unsigned excl = inc - pair;
        if (lane == 31) wsum[warp] = inc;
        __syncthreads();
        if (warp == 0) {
            unsigned v = (lane < 16) ? wsum[lane] : 0u;
            unsigned winc = v;
#pragma unroll
            for (int off = 1; off < 16; off <<= 1) {
                unsigned t = __shfl_up_sync(0xffffffffu, winc, off);
                if (lane >= off) winc += t;
            }
            if (lane < 16) wsum[lane] = winc - v;
        }
        __syncthreads();
        const unsigned basepair = excl + wsum[warp];
        unsigned gpref = basepair >> 16;
        unsigned epref = basepair & 0xFFFFu;
#pragma unroll
        for (int j = 0; j < 9; j++) {
            const int i = base + j;
            if (i < LC_) {
                const unsigned k = keys_l[j];
                if (k > thr) {
                    out_idx[gpref + (epref < rem ? epref : rem)] = i;
                    gpref++;
                } else if (k == thr) {
                    if (epref < rem) out_idx[gpref + epref] = i;
                    epref++;
                }
            }
        }
        __syncthreads();
        if (tid < KEEP_) g_topidx[b * KEEP_ + tid] = out_idx[tid];
    } else if (blk < 80) {
        // gemv1: proj1[b,e] = sum_d u[b,d]*wread[e,d]; W DRAM read hidden behind topk
        float4* sctx = (float4*)smem_raw;
        const int e = (blk - 16) * 16 + warp;
        const float* wr = wread + (size_t)e * D_ + lane * 4;
        float4 w[8];
#pragma unroll
        for (int k = 0; k < 8; k++)
            w[k] = *(const float4*)(wr + k * 128);

        if (tid == 0) {
            while (atomicAdd(&g_uflag, 0u) < 8u) __nanosleep(32);
        }
        __syncthreads();
        __threadfence();
        for (int i = tid; i < B_ * 256; i += TPB_)
            sctx[i] = ((const float4*)g_u)[i];
        __syncthreads();

        float acc[B_];
#pragma unroll
        for (int bb = 0; bb < B_; bb++) acc[bb] = 0.f;
#pragma unroll
        for (int k = 0; k < 8; k++) {
#pragma unroll
            for (int bb = 0; bb < B_; bb++) {
                float4 c = sctx[bb * 256 + k * 32 + lane];
                acc[bb] += w[k].x * c.x + w[k].y * c.y + w[k].z * c.z + w[k].w * c.w;
            }
        }
#pragma unroll
        for (int bb = 0; bb < B_; bb++) {
#pragma unroll
            for (int o = 16; o > 0; o >>= 1)
                acc[bb] += __shfl_down_sync(0xffffffffu, acc[bb], o);
            if (lane == 0) g_proj1[bb * D_ + e] = acc[bb];
        }
    }
    gbar(1);

    //================ P2: gather kept rows + kept partial column sums ================
    {
        float* s_col = (float*)smem_raw;
        const int b  = blk / BPB_;
        const int sl = blk % BPB_;
        const int row0   = sl * GROWS;
        const int rowend = min(KEEP_, row0 + GROWS);
        for (int i = tid; i < D_; i += TPB_) s_col[i] = 0.f;
        __syncthreads();

        for (int r = row0 + warp; r < rowend; r += 16) {
            const int idx = g_topidx[b * KEEP_ + r];
            const float* src = (idx < A_)
                ? active + ((size_t)b * A_ + idx) * D_
                : x      + ((size_t)b * L_ + (idx - A_)) * D_;
            float* dst = new_active + ((size_t)b * KEEP_ + r) * D_;
            float4 v[8];
#pragma unroll
            for (int k = 0; k < 8; k++)
                v[k] = *(const float4*)(src + k * 128 + lane * 4);
#pragma unroll
            for (int k = 0; k < 8; k++) {
                *(float4*)(dst + k * 128 + lane * 4) = v[k];
                int d0 = k * 128 + lane * 4;
                atomicAdd(&s_col[d0 + 0], v[k].x);
                atomicAdd(&s_col[d0 + 1], v[k].y);
                atomicAdd(&s_col[d0 + 2], v[k].z);
                atomicAdd(&s_col[d0 + 3], v[k].w);
            }
        }
        __syncthreads();
        float* kp = g_kpart + ((size_t)b * GSLICE + sl) * D_;
        for (int i = tid; i < D_ / 4; i += TPB_)
            ((float4*)kp)[i] = ((const float4*)s_col)[i];
    }
    gbar(2);

    //================ P3: kept-reduce (0..7) || gemv2 (8..71); ends at kernel exit ================
    if (blk < 8) {
        const int b = blk;
        for (int d = tid; d < D_; d += TPB_) {
            float ks = 0.f;
            const float* kp = g_kpart + (size_t)b * GSLICE * D_ + d;
#pragma unroll
            for (int s = 0; s < GSLICE; s++) ks += kp[(size_t)s * D_];
            cold_out[b * D_ + d] = g_u[b * D_ + d] - CDROP_ * ks;
            g_kctx[b * D_ + d]   = ALPHA_ * ks;
        }
        __threadfence();
        __syncthreads();
        if (tid == 0) atomicAdd(&g_kflag, 1u);   // release
    } else if (blk < 72) {
        float4* sctx = (float4*)smem_raw;
        const int e = (blk - 8) * 16 + warp;
        const float* wr = wread + (size_t)e * D_ + lane * 4;
        float4 w[8];
#pragma unroll
        for (int k = 0; k < 8; k++)
            w[k] = *(const float4*)(wr + k * 128);       // L2-hot

        if (tid == 0) {
            while (atomicAdd(&g_kflag, 0u) < 8u) __nanosleep(32);
        }
        __syncthreads();
        __threadfence();
        for (int i = tid; i < B_ * 256; i += TPB_)
            sctx[i] = ((const float4*)g_kctx)[i];
        __syncthreads();

        float acc[B_];
#pragma unroll
        for (int bb = 0; bb < B_; bb++) acc[bb] = 0.f;
#pragma unroll
        for (int k = 0; k < 8; k++) {
#pragma unroll
            for (int bb = 0; bb < B_; bb++) {
                float4 c = sctx[bb * 256 + k * 32 + lane];
                acc[bb] += w[k].x * c.x + w[k].y * c.y + w[k].z * c.z + w[k].w * c.w;
            }
        }
#pragma unroll
        for (int bb = 0; bb < B_; bb++) {
#pragma unroll
            for (int o = 16; o > 0; o >>= 1)
                acc[bb] += __shfl_down_sync(0xffffffffu, acc[bb], o);
            if (lane == 0) g_proj[bb * D_ + e] = g_proj1[bb * D_ + e] + acc[bb];
        }
    }
    // no final barrier — kernel boundary synchronizes before k_addproj
}

// ================= K2: addproj, high occupancy =================
// grid (128, 8), block 256 (~40 regs -> 4+ blocks/SM); 32 rows/block, MLP-8
__global__ void __launch_bounds__(256)
k_addproj(const float* __restrict__ x, float* __restrict__ xout) {
    const int b   = blockIdx.y;
    const int l0  = blockIdx.x * 32;
    const int tid = threadIdx.x;
    const float4 p = *(const float4*)(g_proj + b * D_ + tid * 4);
    const float* xs = x    + ((size_t)b * L_ + l0) * D_ + tid * 4;
    float*       os = xout + ((size_t)b * L_ + l0) * D_ + tid * 4;
#pragma unroll
    for (int rr = 0; rr < 32; rr += 8) {
        float4 v[8];
#pragma unroll
        for (int r = 0; r < 8; r++)
            v[r] = *(const float4*)(xs + (size_t)(rr + r) * D_);
#pragma unroll
        for (int r = 0; r < 8; r++) {
            v[r].x += p.x; v[r].y += p.y; v[r].z += p.z; v[r].w += p.w;
            *(float4*)(os + (size_t)(rr + r) * D_) = v[r];
        }
    }
}

// ---------------- launch ----------------
extern "C" void kernel_launch(void* const* d_in, const int* in_sizes, int n_in,
                              void* d_out, int out_size) {
    const float* x      = (const float*)d_in[0];   // [8,4096,1024]
    const float* active = (const float*)d_in[1];   // [8,256,1024]
    const float* cold   = (const float*)d_in[2];   // [8,1024]
    const float* w_sal  = (const float*)d_in[3];   // [1024]
    const float* w_read = (const float*)d_in[4];   // [1024,1024]

    float* xout       = (float*)d_out;
    float* new_active = xout + (size_t)in_sizes[0];
    float* cold_out   = new_active + (size_t)in_sizes[1];

    k_init<<<1, 32>>>();
    k_fused<<<GRID_, TPB_>>>(x, active, cold, w_sal, w_read,
                             new_active, cold_out);
    { dim3 grid(L_ / 32, B_); k_addproj<<<grid, 256>>>(x, xout); }
}

// round 15
// speedup vs baseline: 1.1473x; 1.0172x over previous
#include <cuda_runtime.h>
#include <cuda_bf16.h>
#include <stdint.h>

#define B_    8
#define L_    4096
#define D_    1024
#define A_    256
#define LC_   4352      // A_ + L_
#define KEEP_ 256
#define GRID_ 144       // <= SM count; one block per SM guaranteed
#define TPB_  512
#define BPB_  18        // blocks per batch (144/8)
#define NSLICE 18
#define GSLICE 18
#define SROWS 242       // ceil(4352/18)
#define GROWS 15        // ceil(256/18)

#define CDROP_ (0.1f / 4096.0f)                    // 0.1 / n_dropped
#define ALPHA_ (1.0f / 256.0f - 0.1f / 4096.0f)    // kept coefficient in ctx

// -------- scratch (device globals; no allocation allowed) --------
// zero-initialized at module load; thereafter reset by k_addproj each call
__device__ unsigned g_barrier[8];
__device__ unsigned g_uflag;      // release: u vector ready
__device__ unsigned g_kflag;      // release: kept ctx ready
__device__ float g_sal[B_ * LC_];
__device__ float g_part[B_ * NSLICE * D_];
__device__ float g_kpart[B_ * GSLICE * D_];
__device__ int   g_topidx[B_ * KEEP_];
__device__ float g_u[B_ * D_];       // 0.9*cold + CDROP*totsum
__device__ float g_kctx[B_ * D_];    // ALPHA*keptsum
__device__ float g_proj1[B_ * D_];   // u @ W^T
__device__ float g_proj[B_ * D_];    // full proj

__device__ __forceinline__ void gbar(int ph) {
    __syncthreads();
    __threadfence();
    if (threadIdx.x == 0) {
        atomicAdd(&g_barrier[ph], 1u);
        while (atomicAdd(&g_barrier[ph], 0u) < (unsigned)GRID_) __nanosleep(32);
        __threadfence();
    }
    __syncthreads();
}

__device__ __forceinline__ unsigned int order_key(float f) {
    unsigned int u = __float_as_uint(f);
    return u ^ ((u >> 31) ? 0xFFFFFFFFu : 0x80000000u);
}

// ================= K1: persistent — salience .. gemv (phases P0..P3) =================
__global__ void __launch_bounds__(TPB_, 1)
k_fused(const float* __restrict__ x,
        const float* __restrict__ active,
        const float* __restrict__ cold,
        const float* __restrict__ wsal,
        const float* __restrict__ wread,
        float* __restrict__ new_active,
        float* __restrict__ cold_out) {
    __shared__ __align__(16) char smem_raw[33024];
    __shared__ unsigned s_prefix;
    __shared__ int s_krem;

    const int blk  = blockIdx.x;
    const int tid  = threadIdx.x;
    const int warp = tid >> 5;
    const int lane = tid & 31;

    //================ P0: salience + per-block partial column sums ================
    {
        float* s_col = (float*)smem_raw;
        const int b  = blk / BPB_;
        const int sl = blk % BPB_;
        for (int i = tid; i < D_; i += TPB_) s_col[i] = 0.f;

        float4 ws[8];
#pragma unroll
        for (int k = 0; k < 8; k++)
            ws[k] = *(const float4*)(wsal + k * 128 + lane * 4);
        float4 cs[8];
#pragma unroll
        for (int k = 0; k < 8; k++) cs[k] = make_float4(0.f, 0.f, 0.f, 0.f);
        __syncthreads();

        const int row0   = sl * SROWS;
        const int rowend = min(LC_, row0 + SROWS);
        for (int t = row0 + warp; t < rowend; t += 16) {
            const float* src = (t < A_)
                ? active + ((size_t)b * A_ + t) * D_
                : x      + ((size_t)b * L_ + (t - A_)) * D_;
            float dot = 0.f;
#pragma unroll
            for (int k = 0; k < 8; k++) {
                float4 v = *(const float4*)(src + k * 128 + lane * 4);
                dot += v.x * ws[k].x + v.y * ws[k].y + v.z * ws[k].z + v.w * ws[k].w;
                cs[k].x += v.x; cs[k].y += v.y; cs[k].z += v.z; cs[k].w += v.w;
            }
#pragma unroll
            for (int o = 16; o > 0; o >>= 1)
                dot += __shfl_down_sync(0xffffffffu, dot, o);
            if (lane == 0) g_sal[b * LC_ + t] = dot;
        }
#pragma unroll
        for (int k = 0; k < 8; k++) {
            int d0 = k * 128 + lane * 4;
            atomicAdd(&s_col[d0 + 0], cs[k].x);
            atomicAdd(&s_col[d0 + 1], cs[k].y);
            atomicAdd(&s_col[d0 + 2], cs[k].z);
            atomicAdd(&s_col[d0 + 3], cs[k].w);
        }
        __syncthreads();
        float* dst = g_part + ((size_t)b * NSLICE + sl) * D_;
        for (int i = tid; i < D_ / 4; i += TPB_)
            ((float4*)dst)[i] = ((const float4*)s_col)[i];
    }
    gbar(0);

    //================ P1: u-reduce (0..7) || topk (8..15) || gemv1 u@W^T (16..79) ================
    if (blk < 8) {
        const int b = blk;
        for (int d = tid; d < D_; d += TPB_) {
            float tot = 0.f;
            const float* p = g_part + (size_t)b * NSLICE * D_ + d;
#pragma unroll
            for (int s = 0; s < NSLICE; s++) tot += p[(size_t)s * D_];
            g_u[b * D_ + d] = 0.9f * cold[b * D_ + d] + CDROP_ * tot;
        }
        __threadfence();
        __syncthreads();
        if (tid == 0) atomicAdd(&g_uflag, 1u);   // release
    } else if (blk < 16) {
        const int b = blk - 8;
        unsigned* skeys = (unsigned*)smem_raw;              // 4352 u32
        unsigned* hist  = (unsigned*)(smem_raw + 17408);
        int* out_idx    = (int*)(smem_raw + 18432);
        unsigned* wsum  = (unsigned*)(smem_raw + 19456);

        for (int i = tid; i < LC_; i += TPB_)
            skeys[i] = order_key(g_sal[b * LC_ + i]);
        if (tid == 0) { s_prefix = 0u; s_krem = KEEP_; }
        __syncthreads();

        for (int pass = 0; pass < 4; pass++) {
            const int shift = 24 - 8 * pass;
            if (tid < 256) hist[tid] = 0u;
            __syncthreads();
            const unsigned pfx = s_prefix;
            const int krem = s_krem;
            for (int i = tid; i < LC_; i += TPB_) {
                unsigned k = skeys[i];
                if (pass == 0 || (k >> (shift + 8)) == pfx)
                    atomicAdd(&hist[(k >> shift) & 255u], 1u);
            }
            __syncthreads();
            if (warp == 0) {
                unsigned h[8], suf[8];
                unsigned acc = 0u;
#pragma unroll
                for (int j = 7; j >= 0; j--) { h[j] = hist[lane * 8 + j]; acc += h[j]; suf[j] = acc; }
                const unsigned tot = acc;
                unsigned inc = tot;
#pragma unroll
                for (int off = 1; off < 32; off <<= 1) {
                    unsigned v = __shfl_down_sync(0xffffffffu, inc, off);
                    if (lane + off < 32) inc += v;
                }
                const unsigned after = inc - tot;
#pragma unroll
                for (int j = 0; j < 8; j++) {
                    unsigned S  = after + suf[j];
                    unsigned Sn = after + (j < 7 ? suf[j + 1] : 0u);
                    if (S >= (unsigned)krem && Sn < (unsigned)krem) {
                        s_prefix = (pfx << 8) | (unsigned)(lane * 8 + j);
                        s_krem   = krem - (int)Sn;
                    }
                }
            }
            __syncthreads();
        }

        const unsigned thr = s_prefix;
        const unsigned rem = (unsigned)s_krem;

        const int base = tid * 9;
        unsigned keys_l[9];
        unsigned gt = 0u, eq = 0u;
#pragma unroll
        for (int j = 0; j < 9; j++) {
            const int i = base + j;
            unsigned k = (i < LC_) ? skeys[i] : 0u;
            keys_l[j] = k;
            if (i < LC_) { gt += (k > thr); eq += (k == thr); }
        }
        const unsigned pair = (gt << 16) | eq;
        unsigned inc = pair;
#pragma unroll
        for (int off = 1; off < 32; off <<= 1) {
            unsigned v = __shfl_up_sync(0xffffffffu, inc, off);
            if (lane >= off) inc += v;
        }
        const unsigned excl = inc - pair;
        if (lane == 31) wsum[warp] = inc;
        __syncthreads();
        if (warp == 0) {
            unsigned v = (lane < 16) ? wsum[lane] : 0u;
            unsigned winc = v;
#pragma unroll
            for (int off = 1; off < 16; off <<= 1) {
                unsigned t = __shfl_up_sync(0xffffffffu, winc, off);
                if (lane >= off) winc += t;
            }
            if (lane < 16) wsum[lane] = winc - v;
        }
        __syncthreads();
        const unsigned basepair = excl + wsum[warp];
        unsigned gpref = basepair >> 16;
        unsigned epref = basepair & 0xFFFFu;
#pragma unroll
        for (int j = 0; j < 9; j++) {
            const int i = base + j;
            if (i < LC_) {
                const unsigned k = keys_l[j];
                if (k > thr) {
                    out_idx[gpref + (epref < rem ? epref : rem)] = i;
                    gpref++;
                } else if (k == thr) {
                    if (epref < rem) out_idx[gpref + epref] = i;
                    epref++;
                }
            }
        }
        __syncthreads();
        if (tid < KEEP_) g_topidx[b * KEEP_ + tid] = out_idx[tid];
    } else if (blk < 80) {
        // gemv1: proj1[b,e] = sum_d u[b,d]*wread[e,d]; W DRAM read hidden behind topk
        float4* sctx = (float4*)smem_raw;
        const int e = (blk - 16) * 16 + warp;
        const float* wr = wread + (size_t)e * D_ + lane * 4;
        float4 w[8];
#pragma unroll
        for (int k = 0; k < 8; k++)
            w[k] = *(const float4*)(wr + k * 128);

        if (tid == 0) {
            while (atomicAdd(&g_uflag, 0u) < 8u) __nanosleep(32);
        }
        __syncthreads();
        __threadfence();
        for (int i = tid; i < B_ * 256; i += TPB_)
            sctx[i] = ((const float4*)g_u)[i];
        __syncthreads();

        float acc[B_];
#pragma unroll
        for (int bb = 0; bb < B_; bb++) acc[bb] = 0.f;
#pragma unroll
        for (int k = 0; k < 8; k++) {
#pragma unroll
            for (int bb = 0; bb < B_; bb++) {
                float4 c = sctx[bb * 256 + k * 32 + lane];
                acc[bb] += w[k].x * c.x + w[k].y * c.y + w[k].z * c.z + w[k].w * c.w;
            }
        }
#pragma unroll
        for (int bb = 0; bb < B_; bb++) {
#pragma unroll
            for (int o = 16; o > 0; o >>= 1)
                acc[bb] += __shfl_down_sync(0xffffffffu, acc[bb], o);
            if (lane == 0) g_proj1[bb * D_ + e] = acc[bb];
        }
    }
    gbar(1);

    //================ P2: gather kept rows + kept partial column sums ================
    {
        float* s_col = (float*)smem_raw;
        const int b  = blk / BPB_;
        const int sl = blk % BPB_;
        const int row0   = sl * GROWS;
        const int rowend = min(KEEP_, row0 + GROWS);
        for (int i = tid; i < D_; i += TPB_) s_col[i] = 0.f;
        __syncthreads();

        for (int r = row0 + warp; r < rowend; r += 16) {
            const int idx = g_topidx[b * KEEP_ + r];
            const float* src = (idx < A_)
                ? active + ((size_t)b * A_ + idx) * D_
                : x      + ((size_t)b * L_ + (idx - A_)) * D_;
            float* dst = new_active + ((size_t)b * KEEP_ + r) * D_;
            float4 v[8];
#pragma unroll
            for (int k = 0; k < 8; k++)
                v[k] = *(const float4*)(src + k * 128 + lane * 4);
#pragma unroll
            for (int k = 0; k < 8; k++) {
                *(float4*)(dst + k * 128 + lane * 4) = v[k];
                int d0 = k * 128 + lane * 4;
                atomicAdd(&s_col[d0 + 0], v[k].x);
                atomicAdd(&s_col[d0 + 1], v[k].y);
                atomicAdd(&s_col[d0 + 2], v[k].z);
                atomicAdd(&s_col[d0 + 3], v[k].w);
            }
        }
        __syncthreads();
        float* kp = g_kpart + ((size_t)b * GSLICE + sl) * D_;
        for (int i = tid; i < D_ / 4; i += TPB_)
            ((float4*)kp)[i] = ((const float4*)s_col)[i];
    }
    gbar(2);

    //================ P3: kept-reduce (0..7) || gemv2 (8..71); ends at kernel exit ================
    if (blk < 8) {
        const int b = blk;
        for (int d = tid; d < D_; d += TPB_) {
            float ks = 0.f;
            const float* kp = g_kpart + (size_t)b * GSLICE * D_ + d;
#pragma unroll
            for (int s = 0; s < GSLICE; s++) ks += kp[(size_t)s * D_];
            cold_out[b * D_ + d] = g_u[b * D_ + d] - CDROP_ * ks;
            g_kctx[b * D_ + d]   = ALPHA_ * ks;
        }
        __threadfence();
        __syncthreads();
        if (tid == 0) atomicAdd(&g_kflag, 1u);   // release
    } else if (blk < 72) {
        float4* sctx = (float4*)smem_raw;
        const int e = (blk - 8) * 16 + warp;
        const float* wr = wread + (size_t)e * D_ + lane * 4;
        float4 w[8];
#pragma unroll
        for (int k = 0; k < 8; k++)
            w[k] = *(const float4*)(wr + k * 128);       // L2-hot

        if (tid == 0) {
            while (atomicAdd(&g_kflag, 0u) < 8u) __nanosleep(32);
        }
        __syncthreads();
        __threadfence();
        for (int i = tid; i < B_ * 256; i += TPB_)
            sctx[i] = ((const float4*)g_kctx)[i];
        __syncthreads();

        float acc[B_];
#pragma unroll
        for (int bb = 0; bb < B_; bb++) acc[bb] = 0.f;
#pragma unroll
        for (int k = 0; k < 8; k++) {
#pragma unroll
            for (int bb = 0; bb < B_; bb++) {
                float4 c = sctx[bb * 256 + k * 32 + lane];
                acc[bb] += w[k].x * c.x + w[k].y * c.y + w[k].z * c.z + w[k].w * c.w;
            }
        }
#pragma unroll
        for (int bb = 0; bb < B_; bb++) {
#pragma unroll
            for (int o = 16; o > 0; o >>= 1)
                acc[bb] += __shfl_down_sync(0xffffffffu, acc[bb], o);
            if (lane == 0) g_proj[bb * D_ + e] = g_proj1[bb * D_ + e] + acc[bb];
        }
    }
    // no final barrier — kernel boundary synchronizes before k_addproj
}

// ================= K2: addproj + barrier/flag reset for next replay =================
// grid (128, 8), block 256; 32 rows/block, MLP-8. Runs after k_fused (stream
// order), so resetting the counters here is safe for the next graph replay.
__global__ void __launch_bounds__(256)
k_addproj(const float* __restrict__ x, float* __restrict__ xout) {
    if (blockIdx.x == 0 && blockIdx.y == 0 && threadIdx.x < 10) {
        if (threadIdx.x < 8)       g_barrier[threadIdx.x] = 0u;
        else if (threadIdx.x == 8) g_uflag = 0u;
        else                       g_kflag = 0u;
    }
    const int b   = blockIdx.y;
    const int l0  = blockIdx.x * 32;
    const int tid = threadIdx.x;
    const float4 p = *(const float4*)(g_proj + b * D_ + tid * 4);
    const float* xs = x    + ((size_t)b * L_ + l0) * D_ + tid * 4;
    float*       os = xout + ((size_t)b * L_ + l0) * D_ + tid * 4;
#pragma unroll
    for (int rr = 0; rr < 32; rr += 8) {
        float4 v[8];
#pragma unroll
        for (int r = 0; r < 8; r++)
            v[r] = *(const float4*)(xs + (size_t)(rr + r) * D_);
#pragma unroll
        for (int r = 0; r < 8; r++) {
            v[r].x += p.x; v[r].y += p.y; v[r].z += p.z; v[r].w += p.w;
            *(float4*)(os + (size_t)(rr + r) * D_) = v[r];
        }
    }
}

// ---------------- launch ----------------
extern "C" void kernel_launch(void* const* d_in, const int* in_sizes, int n_in,
                              void* d_out, int out_size) {
    const float* x      = (const float*)d_in[0];   // [8,4096,1024]
    const float* active = (const float*)d_in[1];   // [8,256,1024]
    const float* cold   = (const float*)d_in[2];   // [8,1024]
    const float* w_sal  = (const float*)d_in[3];   // [1024]
    const float* w_read = (const float*)d_in[4];   // [1024,1024]

    float* xout       = (float*)d_out;
    float* new_active = xout + (size_t)in_sizes[0];
    float* cold_out   = new_active + (size_t)in_sizes[1];

    k_fused<<<GRID_, TPB_>>>(x, active, cold, w_sal, w_read,
                             new_active, cold_out);
    { dim3 grid(L_ / 32, B_); k_addproj<<<grid, 256>>>(x, xout); }
}